// round 2
// baseline (speedup 1.0000x reference)
#include <cuda_runtime.h>
#include <math.h>

#define D   128
#define G   4096
#define S   3
#define MAXN 1000000
#define TILE_M 132   // smem row stride (128 + 4 pad)

// ---------------- device scratch (no allocations allowed) ----------------
__device__ float d_gates[S * MAXN];
__device__ float d_alpha[S * MAXN];
__device__ int   d_segstart[G + 1];
__device__ float d_pooled[S * G * D];

// ---------------- kernel A: gate dots + copy x -> out ----------------
__global__ void k_gate_copy(const float* __restrict__ x,
                            const float* __restrict__ gate_w,
                            const float* __restrict__ gate_b,
                            float* __restrict__ out_x,
                            int N) {
    __shared__ float gw[S * D];
    int tid = threadIdx.x;
    for (int i = tid; i < S * D; i += blockDim.x) gw[i] = gate_w[i];
    __syncthreads();
    int lane = tid & 31;
    int node = blockIdx.x * (blockDim.x >> 5) + (tid >> 5);
    if (node >= N) return;
    const float4 v = ((const float4*)(x + (size_t)node * D))[lane];
    ((float4*)(out_x + (size_t)node * D))[lane] = v;
#pragma unroll
    for (int s = 0; s < S; ++s) {
        const float* g = gw + s * D + lane * 4;
        float d = v.x * g[0] + v.y * g[1] + v.z * g[2] + v.w * g[3];
#pragma unroll
        for (int o = 16; o > 0; o >>= 1) d += __shfl_xor_sync(0xffffffffu, d, o);
        if (lane == 0) d_gates[s * N + node] = d + gate_b[s];
    }
}

// ---------------- small: copy x_global into out xg region ----------------
__global__ void k_copy_xg(const float* __restrict__ xg, float* __restrict__ out_xg) {
    int i = blockIdx.x * blockDim.x + threadIdx.x;
    if (i < G * D) out_xg[i] = xg[i];
}

// ---------------- kernel B: segment starts (batch_ind sorted, int32) ----------------
__global__ void k_segstart(const int* __restrict__ batch, int N) {
    int g = blockIdx.x * blockDim.x + threadIdx.x;
    if (g > G) return;
    if (g == G) { d_segstart[G] = N; return; }
    int lo = 0, hi = N;
    while (lo < hi) {
        int mid = (lo + hi) >> 1;
        if (batch[mid] < g) lo = mid + 1; else hi = mid;
    }
    d_segstart[g] = lo;
}

// ---------------- kernel C: per-graph softmax -> alpha; zero pooled ----------------
__global__ void k_softmax(int N) {
    int g = blockIdx.x, t = threadIdx.x;   // 128 threads
#pragma unroll
    for (int s = 0; s < S; ++s) d_pooled[(s * G + g) * D + t] = 0.f;
    int a = d_segstart[g], b = d_segstart[g + 1];
    if (a >= b) return;

    __shared__ float red[S][4];
    int wid = t >> 5, lane = t & 31;

    float mx[S];
#pragma unroll
    for (int s = 0; s < S; ++s) mx[s] = -INFINITY;
    for (int i = a + t; i < b; i += 128)
#pragma unroll
        for (int s = 0; s < S; ++s) mx[s] = fmaxf(mx[s], d_gates[s * N + i]);
#pragma unroll
    for (int s = 0; s < S; ++s) {
#pragma unroll
        for (int o = 16; o > 0; o >>= 1) mx[s] = fmaxf(mx[s], __shfl_xor_sync(~0u, mx[s], o));
        if (lane == 0) red[s][wid] = mx[s];
    }
    __syncthreads();
#pragma unroll
    for (int s = 0; s < S; ++s)
        mx[s] = fmaxf(fmaxf(red[s][0], red[s][1]), fmaxf(red[s][2], red[s][3]));
    __syncthreads();

    float sm[S] = {0.f, 0.f, 0.f};
    for (int i = a + t; i < b; i += 128)
#pragma unroll
        for (int s = 0; s < S; ++s) sm[s] += expf(d_gates[s * N + i] - mx[s]);
#pragma unroll
    for (int s = 0; s < S; ++s) {
#pragma unroll
        for (int o = 16; o > 0; o >>= 1) sm[s] += __shfl_xor_sync(~0u, sm[s], o);
        if (lane == 0) red[s][wid] = sm[s];
    }
    __syncthreads();
    float inv[S];
#pragma unroll
    for (int s = 0; s < S; ++s)
        inv[s] = 1.f / (red[s][0] + red[s][1] + red[s][2] + red[s][3]);

    for (int i = a + t; i < b; i += 128)
#pragma unroll
        for (int s = 0; s < S; ++s)
            d_alpha[s * N + i] = expf(d_gates[s * N + i] - mx[s]) * inv[s];
}

// ---------------- kernel D: heavy fused feat GEMM + pooled segment sum ----------------
// block: 256 threads, tile = 128 rows x 128 cols, K=128 all in smem.
__global__ void __launch_bounds__(256, 1)
k_feat_pool(const float* __restrict__ x,
            const float* __restrict__ feat_w,
            const float* __restrict__ feat_b,
            const int* __restrict__ batch,
            int N) {
    extern __shared__ float smem[];
    float* As     = smem;                    // [128][TILE_M]  (x tile, row-major [m][k])
    float* Bs     = As + 128 * TILE_M;       // [128][TILE_M]  (W [k][n], reused as staging [m][n])
    float* s_alpha = Bs + 128 * TILE_M;      // [128]
    float* s_bias  = s_alpha + 128;          // [128]
    int*   s_gid   = (int*)(s_bias + 128);   // [128]

    int tid = threadIdx.x;
    int r0 = blockIdx.x * 128;
    int rows = min(128, N - r0);

    // load x tile (guarded)
    {
        int lane = tid & 31, w = tid >> 5;
        for (int r = w * 16; r < w * 16 + 16; ++r) {
            float4 v = make_float4(0.f, 0.f, 0.f, 0.f);
            if (r < rows) v = ((const float4*)(x + (size_t)(r0 + r) * D))[lane];
            float* dst = As + r * TILE_M + lane * 4;
            dst[0] = v.x; dst[1] = v.y; dst[2] = v.z; dst[3] = v.w;
        }
    }
    if (tid < 128) {
        int rr = min(tid, rows - 1);
        s_gid[tid] = batch[r0 + rr];
    }

    int tx = tid & 15, ty = tid >> 4;    // 16 x 16 threads, each 8x8 outputs

    for (int s = 0; s < S; ++s) {
        __syncthreads();   // previous epilogue done / x tile store visible
        {
            const float* W = feat_w + s * D * D;
            int lane = tid & 31, w = tid >> 5;
            for (int r = w * 16; r < w * 16 + 16; ++r) {
                float4 v = ((const float4*)(W + r * D))[lane];
                float* dst = Bs + r * TILE_M + lane * 4;
                dst[0] = v.x; dst[1] = v.y; dst[2] = v.z; dst[3] = v.w;
            }
        }
        if (tid < 128) {
            s_bias[tid]  = feat_b[s * D + tid];
            s_alpha[tid] = (tid < rows) ? d_alpha[s * N + r0 + tid] : 0.f;
        }
        __syncthreads();

        float c[8][8];
#pragma unroll
        for (int i = 0; i < 8; ++i)
#pragma unroll
            for (int j = 0; j < 8; ++j) c[i][j] = 0.f;

#pragma unroll 4
        for (int k = 0; k < D; ++k) {
            float a[8], b[8];
#pragma unroll
            for (int i = 0; i < 8; ++i) a[i] = As[(ty * 8 + i) * TILE_M + k];
            float4 b0 = *(const float4*)(Bs + k * TILE_M + tx * 8);
            float4 b1 = *(const float4*)(Bs + k * TILE_M + tx * 8 + 4);
            b[0] = b0.x; b[1] = b0.y; b[2] = b0.z; b[3] = b0.w;
            b[4] = b1.x; b[5] = b1.y; b[6] = b1.z; b[7] = b1.w;
#pragma unroll
            for (int i = 0; i < 8; ++i)
#pragma unroll
                for (int j = 0; j < 8; ++j) c[i][j] += a[i] * b[j];
        }
        __syncthreads();  // all reads of Bs done before staging overwrite

        // epilogue: v = leaky(c + bias[col]) * alpha[row] -> Bs[row][col]
#pragma unroll
        for (int i = 0; i < 8; ++i) {
            int row = ty * 8 + i;
            float al = s_alpha[row];
            float4 o0, o1;
            float v;
            v = c[i][0] + s_bias[tx * 8 + 0]; v = v >= 0.f ? v : 0.01f * v; o0.x = v * al;
            v = c[i][1] + s_bias[tx * 8 + 1]; v = v >= 0.f ? v : 0.01f * v; o0.y = v * al;
            v = c[i][2] + s_bias[tx * 8 + 2]; v = v >= 0.f ? v : 0.01f * v; o0.z = v * al;
            v = c[i][3] + s_bias[tx * 8 + 3]; v = v >= 0.f ? v : 0.01f * v; o0.w = v * al;
            v = c[i][4] + s_bias[tx * 8 + 4]; v = v >= 0.f ? v : 0.01f * v; o1.x = v * al;
            v = c[i][5] + s_bias[tx * 8 + 5]; v = v >= 0.f ? v : 0.01f * v; o1.y = v * al;
            v = c[i][6] + s_bias[tx * 8 + 6]; v = v >= 0.f ? v : 0.01f * v; o1.z = v * al;
            v = c[i][7] + s_bias[tx * 8 + 7]; v = v >= 0.f ? v : 0.01f * v; o1.w = v * al;
            *(float4*)(Bs + row * TILE_M + tx * 8)     = o0;
            *(float4*)(Bs + row * TILE_M + tx * 8 + 4) = o1;
        }
        __syncthreads();

        // column segment-sums over sorted graph ids, atomic into pooled
        if (tid < D) {
            int col = tid;
            float acc = Bs[col];
            int cg = s_gid[0];
            for (int r = 1; r < rows; ++r) {
                int gr = s_gid[r];
                if (gr != cg) {
                    atomicAdd(&d_pooled[((size_t)s * G + cg) * D + col], acc);
                    acc = 0.f;
                    cg = gr;
                }
                acc += Bs[r * TILE_M + col];
            }
            atomicAdd(&d_pooled[((size_t)s * G + cg) * D + col], acc);
        }
    }
}

// ---------------- kernel E: xg update (in-place per step) ----------------
__global__ void k_xg(const float* __restrict__ tr_w, const float* __restrict__ tr_b,
                     float* __restrict__ xg, int s) {
    __shared__ float cat[2 * D];
    int g = blockIdx.x, t = threadIdx.x;  // 128 threads
    cat[t]     = d_pooled[((size_t)s * G + g) * D + t];
    cat[D + t] = xg[(size_t)g * D + t];
    __syncthreads();
    const float* W = tr_w + (size_t)s * 2 * D * D;
    float acc = tr_b[s * D + t];
#pragma unroll 8
    for (int k = 0; k < 2 * D; ++k)
        acc += cat[k] * W[(size_t)k * D + t];
    acc = acc >= 0.f ? acc : 0.01f * acc;
    xg[(size_t)g * D + t] = acc + cat[D + t];
}

// ---------------- host launcher ----------------
extern "C" void kernel_launch(void* const* d_in, const int* in_sizes, int n_in,
                              void* d_out, int out_size) {
    const float* x   = (const float*)d_in[0];
    const float* xg0 = (const float*)d_in[1];

    int N = in_sizes[0] / D;

    // batch_ind: the unique input with exactly N elements (after x)
    int bi = 4;
    for (int i = 1; i < n_in; ++i)
        if (in_sizes[i] == N) { bi = i; break; }
    const int* batch = (const int*)d_in[bi];

    // weights: find gate_w by the unique (384, 3) adjacent size pattern
    int wi = -1;
    for (int i = 2; i + 5 < n_in; ++i)
        if (in_sizes[i] == S * D && in_sizes[i + 1] == S) { wi = i; break; }
    if (wi < 0) wi = (n_in >= 12) ? 6 : 5;
    const float* gate_w = (const float*)d_in[wi];
    const float* gate_b = (const float*)d_in[wi + 1];
    const float* feat_w = (const float*)d_in[wi + 2];
    const float* feat_b = (const float*)d_in[wi + 3];
    const float* tr_w   = (const float*)d_in[wi + 4];
    const float* tr_b   = (const float*)d_in[wi + 5];

    float* out_x  = (float*)d_out;
    float* out_xg = out_x + (size_t)N * D;

    const int SMEM_BYTES = (128 * TILE_M * 2 + 3 * 128) * (int)sizeof(float);
    cudaFuncSetAttribute(k_feat_pool, cudaFuncAttributeMaxDynamicSharedMemorySize, SMEM_BYTES);

    k_gate_copy<<<(N + 7) / 8, 256>>>(x, gate_w, gate_b, out_x, N);
    k_copy_xg<<<(G * D + 255) / 256, 256>>>(xg0, out_xg);
    k_segstart<<<(G + 128) / 128, 128>>>(batch, N);
    k_softmax<<<G, 128>>>(N);
    k_feat_pool<<<(N + 127) / 128, 256, SMEM_BYTES>>>(x, feat_w, feat_b, batch, N);
    for (int s = 0; s < S; ++s)
        k_xg<<<G, 128>>>(tr_w, tr_b, out_xg, s);
}

// round 4
// speedup vs baseline: 1.7902x; 1.7902x over previous
#include <cuda_runtime.h>
#include <cuda_bf16.h>
#include <math.h>
#include <stdint.h>

#define D   128
#define G   4096
#define S   3
#define MAXN 1000000

// ---------------- device scratch ----------------
__device__ float d_gates[S * MAXN];
__device__ float d_alpha[S * MAXN];
__device__ int   d_segstart[G + 1];
__device__ float d_pooled[S * G * D];
__device__ __nv_bfloat16 d_wt_hi[S * D * D];   // W^T split-hi  [s][n][k]
__device__ __nv_bfloat16 d_wt_lo[S * D * D];   // W^T split-lo

// ---------------- helpers ----------------
__device__ __forceinline__ uint32_t smem_u32(const void* p) {
    uint32_t a;
    asm("{ .reg .u64 t; cvta.to.shared.u64 t, %1; cvt.u32.u64 %0, t; }" : "=r"(a) : "l"(p));
    return a;
}

__device__ __forceinline__ void ldsm_x4(uint32_t* r, uint32_t addr) {
    asm volatile("ldmatrix.sync.aligned.m8n8.x4.shared.b16 {%0,%1,%2,%3}, [%4];"
                 : "=r"(r[0]), "=r"(r[1]), "=r"(r[2]), "=r"(r[3]) : "r"(addr));
}

__device__ __forceinline__ void mma16816(float* c, const uint32_t* a, uint32_t b0, uint32_t b1) {
    asm volatile(
        "mma.sync.aligned.m16n8k16.row.col.f32.bf16.bf16.f32 "
        "{%0,%1,%2,%3}, {%4,%5,%6,%7}, {%8,%9}, {%0,%1,%2,%3};"
        : "+f"(c[0]), "+f"(c[1]), "+f"(c[2]), "+f"(c[3])
        : "r"(a[0]), "r"(a[1]), "r"(a[2]), "r"(a[3]), "r"(b0), "r"(b1));
}

// swizzled byte offset within a [128 row][128 bf16] tile: row stride 256B,
// XOR bits[4:6] with row&7 -> ldmatrix conflict-free.
__device__ __forceinline__ uint32_t swz(int row, int kbyte) {
    return ((uint32_t)row << 8) + ((uint32_t)kbyte ^ (((uint32_t)row & 7u) << 4));
}

// ---------------- smem layout (bytes) ----------------
#define SM_A_HI   0
#define SM_A_LO   32768
#define SM_B_HI   65536
#define SM_B_LO   98304
#define SM_STG    131072            // 128 x 129 fp32 = 66048
#define SM_ALPHA  197120
#define SM_BIAS   197632
#define SM_GID    198144
#define SMEM_TOTAL 198656
#define STG_LD    129

// ---------------- kernel A: gate dots + copy x -> out ----------------
__global__ void k_gate_copy(const float* __restrict__ x,
                            const float* __restrict__ gate_w,
                            const float* __restrict__ gate_b,
                            float* __restrict__ out_x, int N) {
    __shared__ float gw[S * D];
    int tid = threadIdx.x;
    for (int i = tid; i < S * D; i += blockDim.x) gw[i] = gate_w[i];
    __syncthreads();
    int lane = tid & 31;
    int node = blockIdx.x * (blockDim.x >> 5) + (tid >> 5);
    if (node >= N) return;
    const float4 v = ((const float4*)(x + (size_t)node * D))[lane];
    ((float4*)(out_x + (size_t)node * D))[lane] = v;
#pragma unroll
    for (int s = 0; s < S; ++s) {
        const float* g = gw + s * D + lane * 4;
        float d = v.x * g[0] + v.y * g[1] + v.z * g[2] + v.w * g[3];
#pragma unroll
        for (int o = 16; o > 0; o >>= 1) d += __shfl_xor_sync(0xffffffffu, d, o);
        if (lane == 0) d_gates[s * N + node] = d + gate_b[s];
    }
}

__global__ void k_copy_xg(const float* __restrict__ xg, float* __restrict__ out_xg) {
    int i = blockIdx.x * blockDim.x + threadIdx.x;
    if (i < G * D) out_xg[i] = xg[i];
}

// ---------------- prep: transpose + split feat_w -> bf16 hi/lo ----------------
__global__ void k_prep_w(const float* __restrict__ feat_w) {
    int i = blockIdx.x * blockDim.x + threadIdx.x;
    if (i >= S * D * D) return;
    int s = i / (D * D), r = i % (D * D);
    int n = r / D, k = r % D;
    float w = feat_w[s * D * D + k * D + n];
    __nv_bfloat16 hi = __float2bfloat16_rn(w);
    __nv_bfloat16 lo = __float2bfloat16_rn(w - __bfloat162float(hi));
    d_wt_hi[i] = hi;
    d_wt_lo[i] = lo;
}

// ---------------- kernel B: segment starts ----------------
__global__ void k_segstart(const int* __restrict__ batch, int N) {
    int g = blockIdx.x * blockDim.x + threadIdx.x;
    if (g > G) return;
    if (g == G) { d_segstart[G] = N; return; }
    int lo = 0, hi = N;
    while (lo < hi) {
        int mid = (lo + hi) >> 1;
        if (batch[mid] < g) lo = mid + 1; else hi = mid;
    }
    d_segstart[g] = lo;
}

// ---------------- kernel C: per-graph softmax -> alpha; zero pooled ----------------
__global__ void k_softmax(int N) {
    int g = blockIdx.x, t = threadIdx.x;
#pragma unroll
    for (int s = 0; s < S; ++s) d_pooled[(s * G + g) * D + t] = 0.f;
    int a = d_segstart[g], b = d_segstart[g + 1];
    if (a >= b) return;
    __shared__ float red[S][4];
    int wid = t >> 5, lane = t & 31;
    float mx[S];
#pragma unroll
    for (int s = 0; s < S; ++s) mx[s] = -INFINITY;
    for (int i = a + t; i < b; i += 128)
#pragma unroll
        for (int s = 0; s < S; ++s) mx[s] = fmaxf(mx[s], d_gates[s * N + i]);
#pragma unroll
    for (int s = 0; s < S; ++s) {
#pragma unroll
        for (int o = 16; o > 0; o >>= 1) mx[s] = fmaxf(mx[s], __shfl_xor_sync(~0u, mx[s], o));
        if (lane == 0) red[s][wid] = mx[s];
    }
    __syncthreads();
#pragma unroll
    for (int s = 0; s < S; ++s)
        mx[s] = fmaxf(fmaxf(red[s][0], red[s][1]), fmaxf(red[s][2], red[s][3]));
    __syncthreads();
    float sm[S] = {0.f, 0.f, 0.f};
    for (int i = a + t; i < b; i += 128)
#pragma unroll
        for (int s = 0; s < S; ++s) sm[s] += expf(d_gates[s * N + i] - mx[s]);
#pragma unroll
    for (int s = 0; s < S; ++s) {
#pragma unroll
        for (int o = 16; o > 0; o >>= 1) sm[s] += __shfl_xor_sync(~0u, sm[s], o);
        if (lane == 0) red[s][wid] = sm[s];
    }
    __syncthreads();
    float inv[S];
#pragma unroll
    for (int s = 0; s < S; ++s)
        inv[s] = 1.f / (red[s][0] + red[s][1] + red[s][2] + red[s][3]);
    for (int i = a + t; i < b; i += 128)
#pragma unroll
        for (int s = 0; s < S; ++s)
            d_alpha[s * N + i] = expf(d_gates[s * N + i] - mx[s]) * inv[s];
}

// ---------------- kernel D: HMMA bf16x3 feat GEMM + pooled segment sum ----------------
__global__ void __launch_bounds__(256, 1)
k_feat_pool(const float* __restrict__ x,
            const float* __restrict__ feat_b,
            const int* __restrict__ batch, int N) {
    extern __shared__ char smem[];
    uint32_t sm = smem_u32(smem);
    float* stg     = (float*)(smem + SM_STG);
    float* s_alpha = (float*)(smem + SM_ALPHA);
    float* s_bias  = (float*)(smem + SM_BIAS);
    int*   s_gid   = (int*)(smem + SM_GID);

    int tid = threadIdx.x;
    int wid = tid >> 5, lane = tid & 31;
    int r0 = blockIdx.x * 128;
    int rows = min(128, N - r0);

    // load x tile, split fp32 -> bf16 hi/lo into swizzled smem
#pragma unroll
    for (int i = 0; i < 16; ++i) {
        int idx = i * 256 + tid;           // 4096 float4
        int row = idx >> 5, j = idx & 31;  // k0 = j*4
        float4 v = make_float4(0.f, 0.f, 0.f, 0.f);
        if (row < rows) v = ((const float4*)(x + (size_t)(r0 + row) * D))[j];
        __nv_bfloat16 h0 = __float2bfloat16_rn(v.x), h1 = __float2bfloat16_rn(v.y);
        __nv_bfloat16 h2 = __float2bfloat16_rn(v.z), h3 = __float2bfloat16_rn(v.w);
        __nv_bfloat16 l0 = __float2bfloat16_rn(v.x - __bfloat162float(h0));
        __nv_bfloat16 l1 = __float2bfloat16_rn(v.y - __bfloat162float(h1));
        __nv_bfloat16 l2 = __float2bfloat16_rn(v.z - __bfloat162float(h2));
        __nv_bfloat16 l3 = __float2bfloat16_rn(v.w - __bfloat162float(h3));
        uint2 hp, lp;
        hp.x = (uint32_t)__bfloat16_as_ushort(h0) | ((uint32_t)__bfloat16_as_ushort(h1) << 16);
        hp.y = (uint32_t)__bfloat16_as_ushort(h2) | ((uint32_t)__bfloat16_as_ushort(h3) << 16);
        lp.x = (uint32_t)__bfloat16_as_ushort(l0) | ((uint32_t)__bfloat16_as_ushort(l1) << 16);
        lp.y = (uint32_t)__bfloat16_as_ushort(l2) | ((uint32_t)__bfloat16_as_ushort(l3) << 16);
        uint32_t off = swz(row, j * 8);
        *(uint2*)(smem + SM_A_HI + off) = hp;
        *(uint2*)(smem + SM_A_LO + off) = lp;
    }
    if (tid < 128) {
        int rr = min(tid, rows - 1);
        s_gid[tid] = batch[r0 + rr];
    }

    // warp tiling: 4 m-blocks x 2 n-blocks
    int mbase = (wid & 3) * 32;
    int nbase = (wid >> 2) * 64;
    int r15 = lane & 15;
    uint32_t swx = ((uint32_t)lane & 7u) << 4;
    int khalf = (lane >> 4) << 4;

#pragma unroll 1
    for (int s = 0; s < S; ++s) {
        __syncthreads();   // prev pooling done; B smem reusable
        // load W^T hi/lo (16B chunks, swizzled placement)
        {
            const uint4* wh = (const uint4*)(d_wt_hi + s * D * D);
            const uint4* wl = (const uint4*)(d_wt_lo + s * D * D);
#pragma unroll
            for (int i = 0; i < 8; ++i) {
                int idx = i * 256 + tid;            // 2048 uint4 per buffer
                int row = idx >> 4, kb = (idx & 15) * 16;
                uint32_t off = swz(row, kb);
                *(uint4*)(smem + SM_B_HI + off) = wh[idx];
                *(uint4*)(smem + SM_B_LO + off) = wl[idx];
            }
        }
        if (tid < 128) {
            s_bias[tid]  = feat_b[s * D + tid];
            s_alpha[tid] = (tid < rows) ? d_alpha[s * N + r0 + tid] : 0.f;
        }
        __syncthreads();

        float c[16][4];   // [mi*8+nt][4]
#pragma unroll
        for (int i = 0; i < 16; ++i)
#pragma unroll
            for (int j = 0; j < 4; ++j) c[i][j] = 0.f;

#pragma unroll
        for (int ks = 0; ks < 8; ++ks) {
            int kb = ks * 32 + khalf;
            uint32_t ah[2][4], al[2][4];
#pragma unroll
            for (int mi = 0; mi < 2; ++mi) {
                uint32_t roff = ((uint32_t)(mbase + mi * 16 + r15) << 8) + ((uint32_t)kb ^ swx);
                ldsm_x4(ah[mi], sm + SM_A_HI + roff);
                ldsm_x4(al[mi], sm + SM_A_LO + roff);
            }
#pragma unroll
            for (int nq = 0; nq < 4; ++nq) {
                uint32_t bh[4], bl[4];
                uint32_t roff = ((uint32_t)(nbase + nq * 16 + r15) << 8) + ((uint32_t)kb ^ swx);
                ldsm_x4(bh, sm + SM_B_HI + roff);
                ldsm_x4(bl, sm + SM_B_LO + roff);
#pragma unroll
                for (int mi = 0; mi < 2; ++mi) {
                    float* c0 = c[mi * 8 + nq * 2];
                    float* c1 = c[mi * 8 + nq * 2 + 1];
                    mma16816(c0, ah[mi], bh[0], bh[2]);
                    mma16816(c1, ah[mi], bh[1], bh[3]);
                    mma16816(c0, ah[mi], bl[0], bl[2]);
                    mma16816(c1, ah[mi], bl[1], bl[3]);
                    mma16816(c0, al[mi], bh[0], bh[2]);
                    mma16816(c1, al[mi], bh[1], bh[3]);
                }
            }
        }

        // epilogue: bias + leaky + alpha -> staging
        {
            int g = lane >> 2, tc = (lane & 3) * 2;
#pragma unroll
            for (int mi = 0; mi < 2; ++mi) {
                int row0 = mbase + mi * 16 + g;
                float a0 = s_alpha[row0], a1 = s_alpha[row0 + 8];
#pragma unroll
                for (int nt = 0; nt < 8; ++nt) {
                    int col = nbase + nt * 8 + tc;
                    float b0 = s_bias[col], b1 = s_bias[col + 1];
                    float* C = c[mi * 8 + nt];
                    float v;
                    v = C[0] + b0; v = v >= 0.f ? v : 0.01f * v; stg[row0 * STG_LD + col]           = v * a0;
                    v = C[1] + b1; v = v >= 0.f ? v : 0.01f * v; stg[row0 * STG_LD + col + 1]       = v * a0;
                    v = C[2] + b0; v = v >= 0.f ? v : 0.01f * v; stg[(row0 + 8) * STG_LD + col]     = v * a1;
                    v = C[3] + b1; v = v >= 0.f ? v : 0.01f * v; stg[(row0 + 8) * STG_LD + col + 1] = v * a1;
                }
            }
        }
        __syncthreads();

        // pooling: 256 threads, 2 row-halves per column
        {
            int col = tid & 127, half = tid >> 7;
            int rb = half ? (rows >> 1) : 0;
            int re = half ? rows : (rows >> 1);
            if (re > rb) {
                float acc = stg[rb * STG_LD + col];
                int cg = s_gid[rb];
                for (int r = rb + 1; r < re; ++r) {
                    int gr = s_gid[r];
                    if (gr != cg) {
                        atomicAdd(&d_pooled[((size_t)s * G + cg) * D + col], acc);
                        acc = 0.f; cg = gr;
                    }
                    acc += stg[r * STG_LD + col];
                }
                atomicAdd(&d_pooled[((size_t)s * G + cg) * D + col], acc);
            }
        }
    }
}

// ---------------- kernel E: xg update, 16 graphs per block ----------------
#define XG_B 16
__global__ void k_xg(const float* __restrict__ tr_w, const float* __restrict__ tr_b,
                     float* __restrict__ xg, int s) {
    __shared__ float cat[XG_B][2 * D];
    int t = threadIdx.x;                 // 128 threads (= output col)
    int g0 = blockIdx.x * XG_B;
#pragma unroll
    for (int q = 0; q < XG_B; ++q) {
        cat[q][t]     = d_pooled[((size_t)s * G + g0 + q) * D + t];
        cat[q][D + t] = xg[(size_t)(g0 + q) * D + t];
    }
    __syncthreads();
    const float* W = tr_w + (size_t)s * 2 * D * D;
    float bias = tr_b[s * D + t];
    float acc[XG_B];
#pragma unroll
    for (int q = 0; q < XG_B; ++q) acc[q] = bias;
    for (int k = 0; k < 2 * D; ++k) {
        float w = W[(size_t)k * D + t];
#pragma unroll
        for (int q = 0; q < XG_B; ++q) acc[q] += cat[q][k] * w;
    }
#pragma unroll
    for (int q = 0; q < XG_B; ++q) {
        float v = acc[q] >= 0.f ? acc[q] : 0.01f * acc[q];
        xg[(size_t)(g0 + q) * D + t] = v + cat[q][D + t];
    }
}

// ---------------- host launcher ----------------
extern "C" void kernel_launch(void* const* d_in, const int* in_sizes, int n_in,
                              void* d_out, int out_size) {
    const float* x   = (const float*)d_in[0];
    const float* xg0 = (const float*)d_in[1];
    int N = in_sizes[0] / D;

    int bi = 4;
    for (int i = 1; i < n_in; ++i)
        if (in_sizes[i] == N) { bi = i; break; }
    const int* batch = (const int*)d_in[bi];

    int wi = -1;
    for (int i = 2; i + 5 < n_in; ++i)
        if (in_sizes[i] == S * D && in_sizes[i + 1] == S) { wi = i; break; }
    if (wi < 0) wi = (n_in >= 12) ? 6 : 5;
    const float* gate_w = (const float*)d_in[wi];
    const float* gate_b = (const float*)d_in[wi + 1];
    const float* feat_w = (const float*)d_in[wi + 2];
    const float* feat_b = (const float*)d_in[wi + 3];
    const float* tr_w   = (const float*)d_in[wi + 4];
    const float* tr_b   = (const float*)d_in[wi + 5];

    float* out_x  = (float*)d_out;
    float* out_xg = out_x + (size_t)N * D;

    cudaFuncSetAttribute(k_feat_pool, cudaFuncAttributeMaxDynamicSharedMemorySize, SMEM_TOTAL);

    k_gate_copy<<<(N + 7) / 8, 256>>>(x, gate_w, gate_b, out_x, N);
    k_copy_xg<<<(G * D + 255) / 256, 256>>>(xg0, out_xg);
    k_prep_w<<<(S * D * D + 255) / 256, 256>>>(feat_w);
    k_segstart<<<(G + 128) / 128, 128>>>(batch, N);
    k_softmax<<<G, 128>>>(N);
    k_feat_pool<<<(N + 127) / 128, 256, SMEM_TOTAL>>>(x, feat_b, batch, N);
    for (int s = 0; s < S; ++s)
        k_xg<<<G / XG_B, 128>>>(tr_w, tr_b, out_xg, s);
}

// round 6
// speedup vs baseline: 2.0254x; 1.1314x over previous
#include <cuda_runtime.h>
#include <cuda_bf16.h>
#include <math.h>
#include <stdint.h>

#define D   128
#define G   4096
#define S   3
#define MAXN 1000000

// ---------------- device scratch ----------------
__device__ float d_gates[S * MAXN];
__device__ float d_alpha[S * MAXN];
__device__ int   d_segstart[G + 1];
__device__ float d_pooled[S * G * D];
__device__ __nv_bfloat16 d_wt_hi[S * D * D];   // W^T split-hi  [s][n][k]
__device__ __nv_bfloat16 d_wt_lo[S * D * D];   // W^T split-lo

// ---------------- helpers ----------------
__device__ __forceinline__ uint32_t smem_u32(const void* p) {
    uint32_t a;
    asm("{ .reg .u64 t; cvta.to.shared.u64 t, %1; cvt.u32.u64 %0, t; }" : "=r"(a) : "l"(p));
    return a;
}

__device__ __forceinline__ void ldsm_x4(uint32_t* r, uint32_t addr) {
    asm volatile("ldmatrix.sync.aligned.m8n8.x4.shared.b16 {%0,%1,%2,%3}, [%4];"
                 : "=r"(r[0]), "=r"(r[1]), "=r"(r[2]), "=r"(r[3]) : "r"(addr));
}

__device__ __forceinline__ void mma16816(float* c, const uint32_t* a, uint32_t b0, uint32_t b1) {
    asm volatile(
        "mma.sync.aligned.m16n8k16.row.col.f32.bf16.bf16.f32 "
        "{%0,%1,%2,%3}, {%4,%5,%6,%7}, {%8,%9}, {%0,%1,%2,%3};"
        : "+f"(c[0]), "+f"(c[1]), "+f"(c[2]), "+f"(c[3])
        : "r"(a[0]), "r"(a[1]), "r"(a[2]), "r"(a[3]), "r"(b0), "r"(b1));
}

// swizzled byte offset within a [128 row][128 bf16] tile (row stride 256B)
__device__ __forceinline__ uint32_t swz(int row, int kbyte) {
    return ((uint32_t)row << 8) + ((uint32_t)kbyte ^ (((uint32_t)row & 7u) << 4));
}
// staging index (floats) in 64x128 fp32 buffer, conflict-free rows+cols
__device__ __forceinline__ uint32_t stg_idx(int row, int col) {
    return (((uint32_t)row & 63u) << 7) + ((uint32_t)col ^ ((uint32_t)row & 31u));
}

// ---------------- smem layout (bytes) ----------------
#define SM_A_HI   0
#define SM_A_LO   32768
#define SM_B      65536          // 32KB: B_hi, then B_lo, then staging (aliased)
#define SM_ALPHA  98304
#define SM_BIAS   98816
#define SM_GID    99328
#define SMEM_TOTAL 99840

// ---------------- kernel A: gate dots + copy x -> out ----------------
__global__ void k_gate_copy(const float* __restrict__ x,
                            const float* __restrict__ gate_w,
                            const float* __restrict__ gate_b,
                            float* __restrict__ out_x, int N) {
    __shared__ float gw[S * D];
    int tid = threadIdx.x;
    for (int i = tid; i < S * D; i += blockDim.x) gw[i] = gate_w[i];
    __syncthreads();
    int lane = tid & 31;
    int node = blockIdx.x * (blockDim.x >> 5) + (tid >> 5);
    if (node >= N) return;
    const float4 v = ((const float4*)(x + (size_t)node * D))[lane];
    ((float4*)(out_x + (size_t)node * D))[lane] = v;
#pragma unroll
    for (int s = 0; s < S; ++s) {
        const float* g = gw + s * D + lane * 4;
        float d = v.x * g[0] + v.y * g[1] + v.z * g[2] + v.w * g[3];
#pragma unroll
        for (int o = 16; o > 0; o >>= 1) d += __shfl_xor_sync(0xffffffffu, d, o);
        if (lane == 0) d_gates[s * N + node] = d + gate_b[s];
    }
}

__global__ void k_copy_xg(const float* __restrict__ xg, float* __restrict__ out_xg) {
    int i = blockIdx.x * blockDim.x + threadIdx.x;
    if (i < G * D) out_xg[i] = xg[i];
}

// ---------------- prep: transpose + split feat_w -> bf16 hi/lo ----------------
__global__ void k_prep_w(const float* __restrict__ feat_w) {
    int i = blockIdx.x * blockDim.x + threadIdx.x;
    if (i >= S * D * D) return;
    int s = i / (D * D), r = i % (D * D);
    int n = r / D, k = r % D;
    float w = feat_w[s * D * D + k * D + n];
    __nv_bfloat16 hi = __float2bfloat16_rn(w);
    __nv_bfloat16 lo = __float2bfloat16_rn(w - __bfloat162float(hi));
    d_wt_hi[i] = hi;
    d_wt_lo[i] = lo;
}

// ---------------- kernel B: segment starts ----------------
__global__ void k_segstart(const int* __restrict__ batch, int N) {
    int g = blockIdx.x * blockDim.x + threadIdx.x;
    if (g > G) return;
    if (g == G) { d_segstart[G] = N; return; }
    int lo = 0, hi = N;
    while (lo < hi) {
        int mid = (lo + hi) >> 1;
        if (batch[mid] < g) lo = mid + 1; else hi = mid;
    }
    d_segstart[g] = lo;
}

// ---------------- kernel C: per-graph softmax -> alpha; zero pooled ----------------
__global__ void k_softmax(int N) {
    int g = blockIdx.x, t = threadIdx.x;
#pragma unroll
    for (int s = 0; s < S; ++s) d_pooled[(s * G + g) * D + t] = 0.f;
    int a = d_segstart[g], b = d_segstart[g + 1];
    if (a >= b) return;
    __shared__ float red[S][4];
    int wid = t >> 5, lane = t & 31;
    float mx[S];
#pragma unroll
    for (int s = 0; s < S; ++s) mx[s] = -INFINITY;
    for (int i = a + t; i < b; i += 128)
#pragma unroll
        for (int s = 0; s < S; ++s) mx[s] = fmaxf(mx[s], d_gates[s * N + i]);
#pragma unroll
    for (int s = 0; s < S; ++s) {
#pragma unroll
        for (int o = 16; o > 0; o >>= 1) mx[s] = fmaxf(mx[s], __shfl_xor_sync(~0u, mx[s], o));
        if (lane == 0) red[s][wid] = mx[s];
    }
    __syncthreads();
#pragma unroll
    for (int s = 0; s < S; ++s)
        mx[s] = fmaxf(fmaxf(red[s][0], red[s][1]), fmaxf(red[s][2], red[s][3]));
    __syncthreads();
    float sm[S] = {0.f, 0.f, 0.f};
    for (int i = a + t; i < b; i += 128)
#pragma unroll
        for (int s = 0; s < S; ++s) sm[s] += expf(d_gates[s * N + i] - mx[s]);
#pragma unroll
    for (int s = 0; s < S; ++s) {
#pragma unroll
        for (int o = 16; o > 0; o >>= 1) sm[s] += __shfl_xor_sync(~0u, sm[s], o);
        if (lane == 0) red[s][wid] = sm[s];
    }
    __syncthreads();
    float inv[S];
#pragma unroll
    for (int s = 0; s < S; ++s)
        inv[s] = 1.f / (red[s][0] + red[s][1] + red[s][2] + red[s][3]);
    for (int i = a + t; i < b; i += 128)
#pragma unroll
        for (int s = 0; s < S; ++s)
            d_alpha[s * N + i] = expf(d_gates[s * N + i] - mx[s]) * inv[s];
}

// ---------------- kernel D: HMMA bf16x3, 2 CTAs/SM, aliased B/staging ----------------
__global__ void __launch_bounds__(256, 2)
k_feat_pool(const float* __restrict__ x,
            const float* __restrict__ feat_b,
            const int* __restrict__ batch, int N) {
    extern __shared__ char smem[];
    uint32_t sm = smem_u32(smem);
    float* stg     = (float*)(smem + SM_B);
    float* s_alpha = (float*)(smem + SM_ALPHA);
    float* s_bias  = (float*)(smem + SM_BIAS);
    int*   s_gid   = (int*)(smem + SM_GID);

    int tid = threadIdx.x;
    int wid = tid >> 5, lane = tid & 31;
    int r0 = blockIdx.x * 128;
    int rows = min(128, N - r0);

    // load x tile, split fp32 -> bf16 hi/lo into swizzled smem (zero-padded)
#pragma unroll
    for (int i = 0; i < 16; ++i) {
        int idx = i * 256 + tid;           // 4096 float4
        int row = idx >> 5, j = idx & 31;
        float4 v = make_float4(0.f, 0.f, 0.f, 0.f);
        if (row < rows) v = ((const float4*)(x + (size_t)(r0 + row) * D))[j];
        __nv_bfloat16 h0 = __float2bfloat16_rn(v.x), h1 = __float2bfloat16_rn(v.y);
        __nv_bfloat16 h2 = __float2bfloat16_rn(v.z), h3 = __float2bfloat16_rn(v.w);
        __nv_bfloat16 l0 = __float2bfloat16_rn(v.x - __bfloat162float(h0));
        __nv_bfloat16 l1 = __float2bfloat16_rn(v.y - __bfloat162float(h1));
        __nv_bfloat16 l2 = __float2bfloat16_rn(v.z - __bfloat162float(h2));
        __nv_bfloat16 l3 = __float2bfloat16_rn(v.w - __bfloat162float(h3));
        uint2 hp, lp;
        hp.x = (uint32_t)__bfloat16_as_ushort(h0) | ((uint32_t)__bfloat16_as_ushort(h1) << 16);
        hp.y = (uint32_t)__bfloat16_as_ushort(h2) | ((uint32_t)__bfloat16_as_ushort(h3) << 16);
        lp.x = (uint32_t)__bfloat16_as_ushort(l0) | ((uint32_t)__bfloat16_as_ushort(l1) << 16);
        lp.y = (uint32_t)__bfloat16_as_ushort(l2) | ((uint32_t)__bfloat16_as_ushort(l3) << 16);
        uint32_t off = swz(row, j * 8);
        *(uint2*)(smem + SM_A_HI + off) = hp;
        *(uint2*)(smem + SM_A_LO + off) = lp;
    }
    if (tid < 128) {
        int rr = min(tid, rows - 1);
        s_gid[tid] = batch[r0 + rr];
    }

    // warp tiling: 4 m-blocks x 2 n-blocks
    int mbase = (wid & 3) * 32;
    int nbase = (wid >> 2) * 64;
    int r15 = lane & 15;
    uint32_t swx = ((uint32_t)lane & 7u) << 4;
    int khalf = (lane >> 4) << 4;
    int grp   = lane >> 2, tc = (lane & 3) * 2;
    bool halfA = (wid & 3) < 2;     // warp owns rows 0..63

#pragma unroll 1
    for (int s = 0; s < S; ++s) {
        __syncthreads();   // prev pooling / x-store visible
        // ---- load B_hi ----
        {
            const uint4* wh = (const uint4*)(d_wt_hi + s * D * D);
#pragma unroll
            for (int i = 0; i < 8; ++i) {
                int idx = i * 256 + tid;
                int row = idx >> 4, kb = (idx & 15) * 16;
                *(uint4*)(smem + SM_B + swz(row, kb)) = wh[idx];
            }
        }
        if (tid < 128) {
            s_bias[tid]  = feat_b[s * D + tid];
            s_alpha[tid] = (tid < rows) ? d_alpha[s * N + r0 + tid] : 0.f;
        }
        __syncthreads();

        float c[16][4];
#pragma unroll
        for (int i = 0; i < 16; ++i)
#pragma unroll
            for (int j = 0; j < 4; ++j) c[i][j] = 0.f;

        // ---- passes 1+2: Ahi*Bhi + Alo*Bhi ----
#pragma unroll
        for (int ks = 0; ks < 8; ++ks) {
            int kb = ks * 32 + khalf;
            uint32_t ah[2][4], al[2][4];
#pragma unroll
            for (int mi = 0; mi < 2; ++mi) {
                uint32_t roff = ((uint32_t)(mbase + mi * 16 + r15) << 8) + ((uint32_t)kb ^ swx);
                ldsm_x4(ah[mi], sm + SM_A_HI + roff);
                ldsm_x4(al[mi], sm + SM_A_LO + roff);
            }
#pragma unroll
            for (int nq = 0; nq < 4; ++nq) {
                uint32_t bh[4];
                uint32_t roff = ((uint32_t)(nbase + nq * 16 + r15) << 8) + ((uint32_t)kb ^ swx);
                ldsm_x4(bh, sm + SM_B + roff);
#pragma unroll
                for (int mi = 0; mi < 2; ++mi) {
                    float* c0 = c[mi * 8 + nq * 2];
                    float* c1 = c[mi * 8 + nq * 2 + 1];
                    mma16816(c0, ah[mi], bh[0], bh[2]);
                    mma16816(c1, ah[mi], bh[1], bh[3]);
                    mma16816(c0, al[mi], bh[0], bh[2]);
                    mma16816(c1, al[mi], bh[1], bh[3]);
                }
            }
        }
        __syncthreads();   // B_hi reads done
        // ---- load B_lo ----
        {
            const uint4* wl = (const uint4*)(d_wt_lo + s * D * D);
#pragma unroll
            for (int i = 0; i < 8; ++i) {
                int idx = i * 256 + tid;
                int row = idx >> 4, kb = (idx & 15) * 16;
                *(uint4*)(smem + SM_B + swz(row, kb)) = wl[idx];
            }
        }
        __syncthreads();
        // ---- pass 3: Ahi*Blo ----
#pragma unroll
        for (int ks = 0; ks < 8; ++ks) {
            int kb = ks * 32 + khalf;
            uint32_t ah[2][4];
#pragma unroll
            for (int mi = 0; mi < 2; ++mi) {
                uint32_t roff = ((uint32_t)(mbase + mi * 16 + r15) << 8) + ((uint32_t)kb ^ swx);
                ldsm_x4(ah[mi], sm + SM_A_HI + roff);
            }
#pragma unroll
            for (int nq = 0; nq < 4; ++nq) {
                uint32_t bl[4];
                uint32_t roff = ((uint32_t)(nbase + nq * 16 + r15) << 8) + ((uint32_t)kb ^ swx);
                ldsm_x4(bl, sm + SM_B + roff);
#pragma unroll
                for (int mi = 0; mi < 2; ++mi) {
                    mma16816(c[mi * 8 + nq * 2],     ah[mi], bl[0], bl[2]);
                    mma16816(c[mi * 8 + nq * 2 + 1], ah[mi], bl[1], bl[3]);
                }
            }
        }
        __syncthreads();   // B_lo reads done; B region becomes staging

        // ---- two-phase epilogue + pooling over 64-row halves ----
#pragma unroll
        for (int ph = 0; ph < 2; ++ph) {
            if ((ph == 0) == halfA) {   // phase 0: rows 0-63, phase 1: rows 64-127
#pragma unroll
                for (int mi = 0; mi < 2; ++mi) {
                    int row0 = mbase + mi * 16 + grp;   // GLOBAL row (0..127)
                    float a0 = s_alpha[row0], a1 = s_alpha[row0 + 8];
#pragma unroll
                    for (int nt = 0; nt < 8; ++nt) {
                        int col = nbase + nt * 8 + tc;
                        float b0 = s_bias[col], b1 = s_bias[col + 1];
                        float* C = c[mi * 8 + nt];
                        float v;
                        v = C[0] + b0; v = v >= 0.f ? v : 0.01f * v; stg[stg_idx(row0, col)]         = v * a0;
                        v = C[1] + b1; v = v >= 0.f ? v : 0.01f * v; stg[stg_idx(row0, col + 1)]     = v * a0;
                        v = C[2] + b0; v = v >= 0.f ? v : 0.01f * v; stg[stg_idx(row0 + 8, col)]     = v * a1;
                        v = C[3] + b1; v = v >= 0.f ? v : 0.01f * v; stg[stg_idx(row0 + 8, col + 1)] = v * a1;
                    }
                }
            }
            __syncthreads();
            // pool this 64-row half: 2 threads per column, 32 rows each
            {
                int col = tid & 127, h = tid >> 7;
                int rb = ph * 64 + h * 32, re = rb + 32;
                float acc = stg[stg_idx(rb, col)];
                int cg = s_gid[rb];
                for (int r = rb + 1; r < re; ++r) {
                    int gr = s_gid[r];
                    if (gr != cg) {
                        atomicAdd(&d_pooled[((size_t)s * G + cg) * D + col], acc);
                        acc = 0.f; cg = gr;
                    }
                    acc += stg[stg_idx(r, col)];
                }
                atomicAdd(&d_pooled[((size_t)s * G + cg) * D + col], acc);
            }
            __syncthreads();
        }
    }
}

// ---------------- kernel E: xg update, 16 graphs per block ----------------
#define XG_B 16
__global__ void k_xg(const float* __restrict__ tr_w, const float* __restrict__ tr_b,
                     float* __restrict__ xg, int s) {
    __shared__ float cat[XG_B][2 * D];
    int t = threadIdx.x;
    int g0 = blockIdx.x * XG_B;
#pragma unroll
    for (int q = 0; q < XG_B; ++q) {
        cat[q][t]     = d_pooled[((size_t)s * G + g0 + q) * D + t];
        cat[q][D + t] = xg[(size_t)(g0 + q) * D + t];
    }
    __syncthreads();
    const float* W = tr_w + (size_t)s * 2 * D * D;
    float bias = tr_b[s * D + t];
    float acc[XG_B];
#pragma unroll
    for (int q = 0; q < XG_B; ++q) acc[q] = bias;
    for (int k = 0; k < 2 * D; ++k) {
        float w = W[(size_t)k * D + t];
#pragma unroll
        for (int q = 0; q < XG_B; ++q) acc[q] += cat[q][k] * w;
    }
#pragma unroll
    for (int q = 0; q < XG_B; ++q) {
        float v = acc[q] >= 0.f ? acc[q] : 0.01f * acc[q];
        xg[(size_t)(g0 + q) * D + t] = v + cat[q][D + t];
    }
}

// ---------------- host launcher ----------------
extern "C" void kernel_launch(void* const* d_in, const int* in_sizes, int n_in,
                              void* d_out, int out_size) {
    const float* x   = (const float*)d_in[0];
    const float* xg0 = (const float*)d_in[1];
    int N = in_sizes[0] / D;

    int bi = 4;
    for (int i = 1; i < n_in; ++i)
        if (in_sizes[i] == N) { bi = i; break; }
    const int* batch = (const int*)d_in[bi];

    int wi = -1;
    for (int i = 2; i + 5 < n_in; ++i)
        if (in_sizes[i] == S * D && in_sizes[i + 1] == S) { wi = i; break; }
    if (wi < 0) wi = (n_in >= 12) ? 6 : 5;
    const float* gate_w = (const float*)d_in[wi];
    const float* gate_b = (const float*)d_in[wi + 1];
    const float* feat_w = (const float*)d_in[wi + 2];
    const float* feat_b = (const float*)d_in[wi + 3];
    const float* tr_w   = (const float*)d_in[wi + 4];
    const float* tr_b   = (const float*)d_in[wi + 5];

    float* out_x  = (float*)d_out;
    float* out_xg = out_x + (size_t)N * D;

    cudaFuncSetAttribute(k_feat_pool, cudaFuncAttributeMaxDynamicSharedMemorySize, SMEM_TOTAL);

    k_gate_copy<<<(N + 7) / 8, 256>>>(x, gate_w, gate_b, out_x, N);
    k_copy_xg<<<(G * D + 255) / 256, 256>>>(xg0, out_xg);
    k_prep_w<<<(S * D * D + 255) / 256, 256>>>(feat_w);
    k_segstart<<<(G + 128) / 128, 128>>>(batch, N);
    k_softmax<<<G, 128>>>(N);
    k_feat_pool<<<(N + 127) / 128, 256, SMEM_TOTAL>>>(x, feat_b, batch, N);
    for (int s = 0; s < S; ++s)
        k_xg<<<G / XG_B, 128>>>(tr_w, tr_b, out_xg, s);
}

// round 7
// speedup vs baseline: 2.0533x; 1.0138x over previous
#include <cuda_runtime.h>
#include <cuda_bf16.h>
#include <math.h>
#include <stdint.h>

#define D   128
#define G   4096
#define S   3
#define MAXN 1000000

// ---------------- device scratch ----------------
__device__ float d_gates[S * MAXN];
__device__ float d_alpha[S * MAXN];
__device__ int   d_segstart[G + 1];
__device__ float d_pooled[S * G * D];
__device__ __nv_bfloat16 d_wt_hi[S * D * D];   // W^T split-hi  [s][n][k]
__device__ __nv_bfloat16 d_wt_lo[S * D * D];   // W^T split-lo

// ---------------- helpers ----------------
__device__ __forceinline__ uint32_t smem_u32(const void* p) {
    uint32_t a;
    asm("{ .reg .u64 t; cvta.to.shared.u64 t, %1; cvt.u32.u64 %0, t; }" : "=r"(a) : "l"(p));
    return a;
}

__device__ __forceinline__ void ldsm_x4(uint32_t* r, uint32_t addr) {
    asm volatile("ldmatrix.sync.aligned.m8n8.x4.shared.b16 {%0,%1,%2,%3}, [%4];"
                 : "=r"(r[0]), "=r"(r[1]), "=r"(r[2]), "=r"(r[3]) : "r"(addr));
}

__device__ __forceinline__ void mma16816(float* c, const uint32_t* a, uint32_t b0, uint32_t b1) {
    asm volatile(
        "mma.sync.aligned.m16n8k16.row.col.f32.bf16.bf16.f32 "
        "{%0,%1,%2,%3}, {%4,%5,%6,%7}, {%8,%9}, {%0,%1,%2,%3};"
        : "+f"(c[0]), "+f"(c[1]), "+f"(c[2]), "+f"(c[3])
        : "r"(a[0]), "r"(a[1]), "r"(a[2]), "r"(a[3]), "r"(b0), "r"(b1));
}

// swizzled byte offset within a [128 row][128 bf16] tile (row stride 256B)
__device__ __forceinline__ uint32_t swz(int row, int kbyte) {
    return ((uint32_t)row << 8) + ((uint32_t)kbyte ^ (((uint32_t)row & 7u) << 4));
}
// staging index (floats) in 64x128 fp32 buffer, conflict-free rows+cols
__device__ __forceinline__ uint32_t stg_idx(int row, int col) {
    return (((uint32_t)row & 63u) << 7) + ((uint32_t)col ^ ((uint32_t)row & 31u));
}

// ---------------- smem layout (bytes) ----------------
#define SM_A_HI   0
#define SM_A_LO   32768
#define SM_B      65536          // 32KB: B_hi, then B_lo, then staging (aliased)
#define SM_ALPHA  98304
#define SM_BIAS   98816
#define SM_GID    99328
#define SMEM_TOTAL 99840

// ---------------- kernel A: gate dots + copy x -> out ----------------
__global__ void k_gate_copy(const float* __restrict__ x,
                            const float* __restrict__ gate_w,
                            const float* __restrict__ gate_b,
                            float* __restrict__ out_x, int N) {
    __shared__ float gw[S * D];
    int tid = threadIdx.x;
    for (int i = tid; i < S * D; i += blockDim.x) gw[i] = gate_w[i];
    __syncthreads();
    int lane = tid & 31;
    int node = blockIdx.x * (blockDim.x >> 5) + (tid >> 5);
    if (node >= N) return;
    const float4 v = ((const float4*)(x + (size_t)node * D))[lane];
    ((float4*)(out_x + (size_t)node * D))[lane] = v;
#pragma unroll
    for (int s = 0; s < S; ++s) {
        const float* g = gw + s * D + lane * 4;
        float d = v.x * g[0] + v.y * g[1] + v.z * g[2] + v.w * g[3];
#pragma unroll
        for (int o = 16; o > 0; o >>= 1) d += __shfl_xor_sync(0xffffffffu, d, o);
        if (lane == 0) d_gates[s * N + node] = d + gate_b[s];
    }
}

// ---------------- merged small kernel: copy_xg + prep_w + segstart ----------------
#define MISC_COPY_BLKS  (G * D / 256)            // 2048
#define MISC_PREP_BLKS  ((S * D * D + 255) / 256) // 192
#define MISC_SEG_BLKS   ((G + 256) / 256)         // 17
#define MISC_BLKS (MISC_COPY_BLKS + MISC_PREP_BLKS + MISC_SEG_BLKS)
__global__ void k_misc(const float* __restrict__ xg, float* __restrict__ out_xg,
                       const float* __restrict__ feat_w,
                       const int* __restrict__ batch, int N) {
    int b = blockIdx.x, t = threadIdx.x;
    if (b < MISC_COPY_BLKS) {
        out_xg[b * 256 + t] = xg[b * 256 + t];
    } else if (b < MISC_COPY_BLKS + MISC_PREP_BLKS) {
        int i = (b - MISC_COPY_BLKS) * 256 + t;
        if (i < S * D * D) {
            int s = i / (D * D), r = i % (D * D);
            int n = r / D, k = r % D;
            float w = feat_w[s * D * D + k * D + n];
            __nv_bfloat16 hi = __float2bfloat16_rn(w);
            __nv_bfloat16 lo = __float2bfloat16_rn(w - __bfloat162float(hi));
            d_wt_hi[i] = hi;
            d_wt_lo[i] = lo;
        }
    } else {
        int g = (b - MISC_COPY_BLKS - MISC_PREP_BLKS) * 256 + t;
        if (g > G) return;
        if (g == G) { d_segstart[G] = N; return; }
        int lo = 0, hi = N;
        while (lo < hi) {
            int mid = (lo + hi) >> 1;
            if (batch[mid] < g) lo = mid + 1; else hi = mid;
        }
        d_segstart[g] = lo;
    }
}

// ---------------- kernel C: per-graph softmax -> alpha; zero pooled ----------------
__global__ void k_softmax(int N) {
    int g = blockIdx.x, t = threadIdx.x;
#pragma unroll
    for (int s = 0; s < S; ++s) d_pooled[(s * G + g) * D + t] = 0.f;
    int a = d_segstart[g], b = d_segstart[g + 1];
    if (a >= b) return;
    __shared__ float red[S][4];
    int wid = t >> 5, lane = t & 31;
    float mx[S];
#pragma unroll
    for (int s = 0; s < S; ++s) mx[s] = -INFINITY;
    for (int i = a + t; i < b; i += 128)
#pragma unroll
        for (int s = 0; s < S; ++s) mx[s] = fmaxf(mx[s], d_gates[s * N + i]);
#pragma unroll
    for (int s = 0; s < S; ++s) {
#pragma unroll
        for (int o = 16; o > 0; o >>= 1) mx[s] = fmaxf(mx[s], __shfl_xor_sync(~0u, mx[s], o));
        if (lane == 0) red[s][wid] = mx[s];
    }
    __syncthreads();
#pragma unroll
    for (int s = 0; s < S; ++s)
        mx[s] = fmaxf(fmaxf(red[s][0], red[s][1]), fmaxf(red[s][2], red[s][3]));
    __syncthreads();
    float sm[S] = {0.f, 0.f, 0.f};
    for (int i = a + t; i < b; i += 128)
#pragma unroll
        for (int s = 0; s < S; ++s) sm[s] += expf(d_gates[s * N + i] - mx[s]);
#pragma unroll
    for (int s = 0; s < S; ++s) {
#pragma unroll
        for (int o = 16; o > 0; o >>= 1) sm[s] += __shfl_xor_sync(~0u, sm[s], o);
        if (lane == 0) red[s][wid] = sm[s];
    }
    __syncthreads();
    float inv[S];
#pragma unroll
    for (int s = 0; s < S; ++s)
        inv[s] = 1.f / (red[s][0] + red[s][1] + red[s][2] + red[s][3]);
    for (int i = a + t; i < b; i += 128)
#pragma unroll
        for (int s = 0; s < S; ++s)
            d_alpha[s * N + i] = expf(d_gates[s * N + i] - mx[s]) * inv[s];
}

// ---------------- kernel D: HMMA bf16x3, 512 threads, 2 CTAs/SM ----------------
__global__ void __launch_bounds__(512, 2)
k_feat_pool(const float* __restrict__ x,
            const float* __restrict__ feat_b,
            const int* __restrict__ batch, int N) {
    extern __shared__ char smem[];
    uint32_t sm = smem_u32(smem);
    float* stg     = (float*)(smem + SM_B);
    float* s_alpha = (float*)(smem + SM_ALPHA);
    float* s_bias  = (float*)(smem + SM_BIAS);
    int*   s_gid   = (int*)(smem + SM_GID);

    int tid = threadIdx.x;
    int wid = tid >> 5, lane = tid & 31;
    int r0 = blockIdx.x * 128;
    int rows = min(128, N - r0);

    // load x tile, split fp32 -> bf16 hi/lo into swizzled smem (zero-padded)
#pragma unroll
    for (int i = 0; i < 8; ++i) {
        int idx = i * 512 + tid;           // 4096 float4
        int row = idx >> 5, j = idx & 31;
        float4 v = make_float4(0.f, 0.f, 0.f, 0.f);
        if (row < rows) v = ((const float4*)(x + (size_t)(r0 + row) * D))[j];
        __nv_bfloat16 h0 = __float2bfloat16_rn(v.x), h1 = __float2bfloat16_rn(v.y);
        __nv_bfloat16 h2 = __float2bfloat16_rn(v.z), h3 = __float2bfloat16_rn(v.w);
        __nv_bfloat16 l0 = __float2bfloat16_rn(v.x - __bfloat162float(h0));
        __nv_bfloat16 l1 = __float2bfloat16_rn(v.y - __bfloat162float(h1));
        __nv_bfloat16 l2 = __float2bfloat16_rn(v.z - __bfloat162float(h2));
        __nv_bfloat16 l3 = __float2bfloat16_rn(v.w - __bfloat162float(h3));
        uint2 hp, lp;
        hp.x = (uint32_t)__bfloat16_as_ushort(h0) | ((uint32_t)__bfloat16_as_ushort(h1) << 16);
        hp.y = (uint32_t)__bfloat16_as_ushort(h2) | ((uint32_t)__bfloat16_as_ushort(h3) << 16);
        lp.x = (uint32_t)__bfloat16_as_ushort(l0) | ((uint32_t)__bfloat16_as_ushort(l1) << 16);
        lp.y = (uint32_t)__bfloat16_as_ushort(l2) | ((uint32_t)__bfloat16_as_ushort(l3) << 16);
        uint32_t off = swz(row, j * 8);
        *(uint2*)(smem + SM_A_HI + off) = hp;
        *(uint2*)(smem + SM_A_LO + off) = lp;
    }
    if (tid < 128) {
        int rr = min(tid, rows - 1);
        s_gid[tid] = batch[r0 + rr];
    }

    // warp tiling: 8 m-blocks (16 rows) x 2 n-blocks (64 cols), 16 warps
    int mbase = (wid & 7) * 16;
    int nbase = (wid >> 3) * 64;
    int r15 = lane & 15;
    uint32_t swx = ((uint32_t)lane & 7u) << 4;
    int khalf = (lane >> 4) << 4;
    int grp   = lane >> 2, tc = (lane & 3) * 2;
    bool halfA = (wid & 7) < 4;     // warp owns rows 0..63

#pragma unroll 1
    for (int s = 0; s < S; ++s) {
        __syncthreads();   // prev pooling / x-store visible
        // ---- load B_hi ----
        {
            const uint4* wh = (const uint4*)(d_wt_hi + s * D * D);
#pragma unroll
            for (int i = 0; i < 4; ++i) {
                int idx = i * 512 + tid;
                int row = idx >> 4, kb = (idx & 15) * 16;
                *(uint4*)(smem + SM_B + swz(row, kb)) = wh[idx];
            }
        }
        if (tid < 128) {
            s_bias[tid]  = feat_b[s * D + tid];
            s_alpha[tid] = (tid < rows) ? d_alpha[s * N + r0 + tid] : 0.f;
        }
        __syncthreads();

        float c[8][4];
#pragma unroll
        for (int i = 0; i < 8; ++i)
#pragma unroll
            for (int j = 0; j < 4; ++j) c[i][j] = 0.f;

        // ---- passes 1+2: Ahi*Bhi + Alo*Bhi ----
#pragma unroll
        for (int ks = 0; ks < 8; ++ks) {
            int kb = ks * 32 + khalf;
            uint32_t ah[4], al[4];
            uint32_t aoff = ((uint32_t)(mbase + r15) << 8) + ((uint32_t)kb ^ swx);
            ldsm_x4(ah, sm + SM_A_HI + aoff);
            ldsm_x4(al, sm + SM_A_LO + aoff);
#pragma unroll
            for (int nq = 0; nq < 4; ++nq) {
                uint32_t bh[4];
                uint32_t boff = ((uint32_t)(nbase + nq * 16 + r15) << 8) + ((uint32_t)kb ^ swx);
                ldsm_x4(bh, sm + SM_B + boff);
                mma16816(c[nq * 2],     ah, bh[0], bh[2]);
                mma16816(c[nq * 2 + 1], ah, bh[1], bh[3]);
                mma16816(c[nq * 2],     al, bh[0], bh[2]);
                mma16816(c[nq * 2 + 1], al, bh[1], bh[3]);
            }
        }
        __syncthreads();   // B_hi reads done
        // ---- load B_lo ----
        {
            const uint4* wl = (const uint4*)(d_wt_lo + s * D * D);
#pragma unroll
            for (int i = 0; i < 4; ++i) {
                int idx = i * 512 + tid;
                int row = idx >> 4, kb = (idx & 15) * 16;
                *(uint4*)(smem + SM_B + swz(row, kb)) = wl[idx];
            }
        }
        __syncthreads();
        // ---- pass 3: Ahi*Blo ----
#pragma unroll
        for (int ks = 0; ks < 8; ++ks) {
            int kb = ks * 32 + khalf;
            uint32_t ah[4];
            uint32_t aoff = ((uint32_t)(mbase + r15) << 8) + ((uint32_t)kb ^ swx);
            ldsm_x4(ah, sm + SM_A_HI + aoff);
#pragma unroll
            for (int nq = 0; nq < 4; ++nq) {
                uint32_t bl[4];
                uint32_t boff = ((uint32_t)(nbase + nq * 16 + r15) << 8) + ((uint32_t)kb ^ swx);
                ldsm_x4(bl, sm + SM_B + boff);
                mma16816(c[nq * 2],     ah, bl[0], bl[2]);
                mma16816(c[nq * 2 + 1], ah, bl[1], bl[3]);
            }
        }
        __syncthreads();   // B_lo reads done; B region becomes staging

        // ---- two-phase epilogue + pooling over 64-row halves ----
#pragma unroll
        for (int ph = 0; ph < 2; ++ph) {
            if ((ph == 0) == halfA) {   // phase 0: rows 0-63, phase 1: rows 64-127
                int row0 = mbase + grp;          // GLOBAL row (0..127)
                float a0 = s_alpha[row0], a1 = s_alpha[row0 + 8];
#pragma unroll
                for (int nt = 0; nt < 8; ++nt) {
                    int col = nbase + nt * 8 + tc;
                    float b0 = s_bias[col], b1 = s_bias[col + 1];
                    float* C = c[nt];
                    float v;
                    v = C[0] + b0; v = v >= 0.f ? v : 0.01f * v; stg[stg_idx(row0, col)]         = v * a0;
                    v = C[1] + b1; v = v >= 0.f ? v : 0.01f * v; stg[stg_idx(row0, col + 1)]     = v * a0;
                    v = C[2] + b0; v = v >= 0.f ? v : 0.01f * v; stg[stg_idx(row0 + 8, col)]     = v * a1;
                    v = C[3] + b1; v = v >= 0.f ? v : 0.01f * v; stg[stg_idx(row0 + 8, col + 1)] = v * a1;
                }
            }
            __syncthreads();
            // pool this 64-row half: 4 threads per column, 16 rows each
            {
                int col = tid & 127, q = (tid >> 7) & 3;
                int rb = ph * 64 + q * 16, re = rb + 16;
                float acc = stg[stg_idx(rb, col)];
                int cg = s_gid[rb];
                for (int r = rb + 1; r < re; ++r) {
                    int gr = s_gid[r];
                    if (gr != cg) {
                        atomicAdd(&d_pooled[((size_t)s * G + cg) * D + col], acc);
                        acc = 0.f; cg = gr;
                    }
                    acc += stg[stg_idx(r, col)];
                }
                atomicAdd(&d_pooled[((size_t)s * G + cg) * D + col], acc);
            }
            __syncthreads();
        }
    }
}

// ---------------- kernel E: xg update, 16 graphs per block ----------------
#define XG_B 16
__global__ void k_xg(const float* __restrict__ tr_w, const float* __restrict__ tr_b,
                     float* __restrict__ xg, int s) {
    __shared__ float cat[XG_B][2 * D];
    int t = threadIdx.x;
    int g0 = blockIdx.x * XG_B;
#pragma unroll
    for (int q = 0; q < XG_B; ++q) {
        cat[q][t]     = d_pooled[((size_t)s * G + g0 + q) * D + t];
        cat[q][D + t] = xg[(size_t)(g0 + q) * D + t];
    }
    __syncthreads();
    const float* W = tr_w + (size_t)s * 2 * D * D;
    float bias = tr_b[s * D + t];
    float acc[XG_B];
#pragma unroll
    for (int q = 0; q < XG_B; ++q) acc[q] = bias;
    for (int k = 0; k < 2 * D; ++k) {
        float w = W[(size_t)k * D + t];
#pragma unroll
        for (int q = 0; q < XG_B; ++q) acc[q] += cat[q][k] * w;
    }
#pragma unroll
    for (int q = 0; q < XG_B; ++q) {
        float v = acc[q] >= 0.f ? acc[q] : 0.01f * acc[q];
        xg[(size_t)(g0 + q) * D + t] = v + cat[q][D + t];
    }
}

// ---------------- host launcher ----------------
extern "C" void kernel_launch(void* const* d_in, const int* in_sizes, int n_in,
                              void* d_out, int out_size) {
    const float* x   = (const float*)d_in[0];
    const float* xg0 = (const float*)d_in[1];
    int N = in_sizes[0] / D;

    int bi = 4;
    for (int i = 1; i < n_in; ++i)
        if (in_sizes[i] == N) { bi = i; break; }
    const int* batch = (const int*)d_in[bi];

    int wi = -1;
    for (int i = 2; i + 5 < n_in; ++i)
        if (in_sizes[i] == S * D && in_sizes[i + 1] == S) { wi = i; break; }
    if (wi < 0) wi = (n_in >= 12) ? 6 : 5;
    const float* gate_w = (const float*)d_in[wi];
    const float* gate_b = (const float*)d_in[wi + 1];
    const float* feat_w = (const float*)d_in[wi + 2];
    const float* feat_b = (const float*)d_in[wi + 3];
    const float* tr_w   = (const float*)d_in[wi + 4];
    const float* tr_b   = (const float*)d_in[wi + 5];

    float* out_x  = (float*)d_out;
    float* out_xg = out_x + (size_t)N * D;

    cudaFuncSetAttribute(k_feat_pool, cudaFuncAttributeMaxDynamicSharedMemorySize, SMEM_TOTAL);

    k_gate_copy<<<(N + 7) / 8, 256>>>(x, gate_w, gate_b, out_x, N);
    k_misc<<<MISC_BLKS, 256>>>(xg0, out_xg, feat_w, batch, N);
    k_softmax<<<G, 128>>>(N);
    k_feat_pool<<<(N + 127) / 128, 512, SMEM_TOTAL>>>(x, feat_b, batch, N);
    for (int s = 0; s < S; ++s)
        k_xg<<<G / XG_B, 128>>>(tr_w, tr_b, out_xg, s);
}

// round 8
// speedup vs baseline: 2.5492x; 1.2415x over previous
#include <cuda_runtime.h>
#include <cuda_fp16.h>
#include <math.h>
#include <stdint.h>

#define D   128
#define G   4096
#define S   3
#define MAXN 1000000

// ---------------- device scratch ----------------
__device__ float d_gates[S * MAXN];
__device__ float d_alpha[S * MAXN];
__device__ int   d_segstart[G + 1];
__device__ float d_pooled[S * G * D];
__device__ __half d_wt_hi[S * D * D];   // W^T fp16  [s][n][k]

// ---------------- helpers ----------------
__device__ __forceinline__ uint32_t smem_u32(const void* p) {
    uint32_t a;
    asm("{ .reg .u64 t; cvta.to.shared.u64 t, %1; cvt.u32.u64 %0, t; }" : "=r"(a) : "l"(p));
    return a;
}

__device__ __forceinline__ void ldsm_x4(uint32_t* r, uint32_t addr) {
    asm volatile("ldmatrix.sync.aligned.m8n8.x4.shared.b16 {%0,%1,%2,%3}, [%4];"
                 : "=r"(r[0]), "=r"(r[1]), "=r"(r[2]), "=r"(r[3]) : "r"(addr));
}

__device__ __forceinline__ void mma16816(float* c, const uint32_t* a, uint32_t b0, uint32_t b1) {
    asm volatile(
        "mma.sync.aligned.m16n8k16.row.col.f32.f16.f16.f32 "
        "{%0,%1,%2,%3}, {%4,%5,%6,%7}, {%8,%9}, {%0,%1,%2,%3};"
        : "+f"(c[0]), "+f"(c[1]), "+f"(c[2]), "+f"(c[3])
        : "r"(a[0]), "r"(a[1]), "r"(a[2]), "r"(a[3]), "r"(b0), "r"(b1));
}

// swizzled byte offset within a [128 row][128 fp16] tile (row stride 256B)
__device__ __forceinline__ uint32_t swz(int row, int kbyte) {
    return ((uint32_t)row << 8) + ((uint32_t)kbyte ^ (((uint32_t)row & 7u) << 4));
}
// staging index (floats) in 64x128 fp32 buffer, conflict-free rows+cols
__device__ __forceinline__ uint32_t stg_idx(int row, int col) {
    return (((uint32_t)row & 63u) << 7) + ((uint32_t)col ^ ((uint32_t)row & 31u));
}

// ---------------- smem layout (bytes) ----------------
#define SM_A_HI   0
#define SM_A_LO   32768
#define SM_B      65536          // 32KB: B_hi, aliased as staging after MMA
#define SM_ALPHA  98304
#define SM_BIAS   98816
#define SM_GID    99328
#define SMEM_TOTAL 99840

// ---------------- kernel A: gate dots + copy x -> out ----------------
__global__ void k_gate_copy(const float* __restrict__ x,
                            const float* __restrict__ gate_w,
                            const float* __restrict__ gate_b,
                            float* __restrict__ out_x, int N) {
    __shared__ float gw[S * D];
    int tid = threadIdx.x;
    for (int i = tid; i < S * D; i += blockDim.x) gw[i] = gate_w[i];
    __syncthreads();
    int lane = tid & 31;
    int node = blockIdx.x * (blockDim.x >> 5) + (tid >> 5);
    if (node >= N) return;
    const float4 v = ((const float4*)(x + (size_t)node * D))[lane];
    ((float4*)(out_x + (size_t)node * D))[lane] = v;
#pragma unroll
    for (int s = 0; s < S; ++s) {
        const float* g = gw + s * D + lane * 4;
        float d = v.x * g[0] + v.y * g[1] + v.z * g[2] + v.w * g[3];
#pragma unroll
        for (int o = 16; o > 0; o >>= 1) d += __shfl_xor_sync(0xffffffffu, d, o);
        if (lane == 0) d_gates[s * N + node] = d + gate_b[s];
    }
}

// ---------------- merged small kernel: copy_xg + prep_w + segstart ----------------
#define MISC_COPY_BLKS  (G * D / 256)             // 2048
#define MISC_PREP_BLKS  ((S * D * D + 255) / 256) // 192
#define MISC_SEG_BLKS   ((G + 256) / 256)         // 17
#define MISC_BLKS (MISC_COPY_BLKS + MISC_PREP_BLKS + MISC_SEG_BLKS)
__global__ void k_misc(const float* __restrict__ xg, float* __restrict__ out_xg,
                       const float* __restrict__ feat_w,
                       const int* __restrict__ batch, int N) {
    int b = blockIdx.x, t = threadIdx.x;
    if (b < MISC_COPY_BLKS) {
        out_xg[b * 256 + t] = xg[b * 256 + t];
    } else if (b < MISC_COPY_BLKS + MISC_PREP_BLKS) {
        int i = (b - MISC_COPY_BLKS) * 256 + t;
        if (i < S * D * D) {
            int s = i / (D * D), r = i % (D * D);
            int n = r / D, k = r % D;
            d_wt_hi[i] = __float2half_rn(feat_w[s * D * D + k * D + n]);
        }
    } else {
        int g = (b - MISC_COPY_BLKS - MISC_PREP_BLKS) * 256 + t;
        if (g > G) return;
        if (g == G) { d_segstart[G] = N; return; }
        int lo = 0, hi = N;
        while (lo < hi) {
            int mid = (lo + hi) >> 1;
            if (batch[mid] < g) lo = mid + 1; else hi = mid;
        }
        d_segstart[g] = lo;
    }
}

// ---------------- kernel C: per-graph softmax -> alpha; zero pooled ----------------
__global__ void k_softmax(int N) {
    int g = blockIdx.x, t = threadIdx.x;
#pragma unroll
    for (int s = 0; s < S; ++s) d_pooled[(s * G + g) * D + t] = 0.f;
    int a = d_segstart[g], b = d_segstart[g + 1];
    if (a >= b) return;
    __shared__ float red[S][4];
    int wid = t >> 5, lane = t & 31;
    float mx[S];
#pragma unroll
    for (int s = 0; s < S; ++s) mx[s] = -INFINITY;
    for (int i = a + t; i < b; i += 128)
#pragma unroll
        for (int s = 0; s < S; ++s) mx[s] = fmaxf(mx[s], d_gates[s * N + i]);
#pragma unroll
    for (int s = 0; s < S; ++s) {
#pragma unroll
        for (int o = 16; o > 0; o >>= 1) mx[s] = fmaxf(mx[s], __shfl_xor_sync(~0u, mx[s], o));
        if (lane == 0) red[s][wid] = mx[s];
    }
    __syncthreads();
#pragma unroll
    for (int s = 0; s < S; ++s)
        mx[s] = fmaxf(fmaxf(red[s][0], red[s][1]), fmaxf(red[s][2], red[s][3]));
    __syncthreads();
    float sm[S] = {0.f, 0.f, 0.f};
    for (int i = a + t; i < b; i += 128)
#pragma unroll
        for (int s = 0; s < S; ++s) sm[s] += expf(d_gates[s * N + i] - mx[s]);
#pragma unroll
    for (int s = 0; s < S; ++s) {
#pragma unroll
        for (int o = 16; o > 0; o >>= 1) sm[s] += __shfl_xor_sync(~0u, sm[s], o);
        if (lane == 0) red[s][wid] = sm[s];
    }
    __syncthreads();
    float inv[S];
#pragma unroll
    for (int s = 0; s < S; ++s)
        inv[s] = 1.f / (red[s][0] + red[s][1] + red[s][2] + red[s][3]);
    for (int i = a + t; i < b; i += 128)
#pragma unroll
        for (int s = 0; s < S; ++s)
            d_alpha[s * N + i] = expf(d_gates[s * N + i] - mx[s]) * inv[s];
}

// ---------------- kernel D: HMMA fp16x2, 512 threads, 2 CTAs/SM ----------------
__global__ void __launch_bounds__(512, 2)
k_feat_pool(const float* __restrict__ x,
            const float* __restrict__ feat_b,
            const int* __restrict__ batch, int N) {
    extern __shared__ char smem[];
    uint32_t sm = smem_u32(smem);
    float* stg     = (float*)(smem + SM_B);
    float* s_alpha = (float*)(smem + SM_ALPHA);
    float* s_bias  = (float*)(smem + SM_BIAS);
    int*   s_gid   = (int*)(smem + SM_GID);

    int tid = threadIdx.x;
    int wid = tid >> 5, lane = tid & 31;
    int r0 = blockIdx.x * 128;
    int rows = min(128, N - r0);

    // load x tile, split fp32 -> fp16 hi/lo into swizzled smem (zero-padded)
#pragma unroll
    for (int i = 0; i < 8; ++i) {
        int idx = i * 512 + tid;           // 4096 float4
        int row = idx >> 5, j = idx & 31;
        float4 v = make_float4(0.f, 0.f, 0.f, 0.f);
        if (row < rows) v = ((const float4*)(x + (size_t)(r0 + row) * D))[j];
        __half h0 = __float2half_rn(v.x), h1 = __float2half_rn(v.y);
        __half h2 = __float2half_rn(v.z), h3 = __float2half_rn(v.w);
        __half l0 = __float2half_rn(v.x - __half2float(h0));
        __half l1 = __float2half_rn(v.y - __half2float(h1));
        __half l2 = __float2half_rn(v.z - __half2float(h2));
        __half l3 = __float2half_rn(v.w - __half2float(h3));
        uint2 hp, lp;
        hp.x = (uint32_t)__half_as_ushort(h0) | ((uint32_t)__half_as_ushort(h1) << 16);
        hp.y = (uint32_t)__half_as_ushort(h2) | ((uint32_t)__half_as_ushort(h3) << 16);
        lp.x = (uint32_t)__half_as_ushort(l0) | ((uint32_t)__half_as_ushort(l1) << 16);
        lp.y = (uint32_t)__half_as_ushort(l2) | ((uint32_t)__half_as_ushort(l3) << 16);
        uint32_t off = swz(row, j * 8);
        *(uint2*)(smem + SM_A_HI + off) = hp;
        *(uint2*)(smem + SM_A_LO + off) = lp;
    }
    if (tid < 128) {
        int rr = min(tid, rows - 1);
        s_gid[tid] = batch[r0 + rr];
    }

    // warp tiling: 8 m-blocks (16 rows) x 2 n-blocks (64 cols), 16 warps
    int mbase = (wid & 7) * 16;
    int nbase = (wid >> 3) * 64;
    int r15 = lane & 15;
    uint32_t swx = ((uint32_t)lane & 7u) << 4;
    int khalf = (lane >> 4) << 4;
    int grp   = lane >> 2, tc = (lane & 3) * 2;
    bool halfA = (wid & 7) < 4;     // warp owns rows 0..63

#pragma unroll 1
    for (int s = 0; s < S; ++s) {
        __syncthreads();   // prev pooling / x-store visible; B region free
        // ---- load B (W^T fp16), once per step ----
        {
            const uint4* wh = (const uint4*)(d_wt_hi + s * D * D);
#pragma unroll
            for (int i = 0; i < 4; ++i) {
                int idx = i * 512 + tid;
                int row = idx >> 4, kb = (idx & 15) * 16;
                *(uint4*)(smem + SM_B + swz(row, kb)) = wh[idx];
            }
        }
        if (tid < 128) {
            s_bias[tid]  = feat_b[s * D + tid];
            s_alpha[tid] = (tid < rows) ? d_alpha[s * N + r0 + tid] : 0.f;
        }
        __syncthreads();

        float c[8][4];
#pragma unroll
        for (int i = 0; i < 8; ++i)
#pragma unroll
            for (int j = 0; j < 4; ++j) c[i][j] = 0.f;

        // ---- single fused loop: c += Ahi*B + Alo*B  (= exact x * W_hi) ----
#pragma unroll
        for (int ks = 0; ks < 8; ++ks) {
            int kb = ks * 32 + khalf;
            uint32_t ah[4], al[4];
            uint32_t aoff = ((uint32_t)(mbase + r15) << 8) + ((uint32_t)kb ^ swx);
            ldsm_x4(ah, sm + SM_A_HI + aoff);
            ldsm_x4(al, sm + SM_A_LO + aoff);
#pragma unroll
            for (int nq = 0; nq < 4; ++nq) {
                uint32_t bh[4];
                uint32_t boff = ((uint32_t)(nbase + nq * 16 + r15) << 8) + ((uint32_t)kb ^ swx);
                ldsm_x4(bh, sm + SM_B + boff);
                mma16816(c[nq * 2],     ah, bh[0], bh[2]);
                mma16816(c[nq * 2 + 1], ah, bh[1], bh[3]);
                mma16816(c[nq * 2],     al, bh[0], bh[2]);
                mma16816(c[nq * 2 + 1], al, bh[1], bh[3]);
            }
        }
        __syncthreads();   // B reads done; B region becomes staging

        // ---- two-phase epilogue + pooling over 64-row halves ----
#pragma unroll
        for (int ph = 0; ph < 2; ++ph) {
            if ((ph == 0) == halfA) {   // phase 0: rows 0-63, phase 1: rows 64-127
                int row0 = mbase + grp;          // GLOBAL row (0..127)
                float a0 = s_alpha[row0], a1 = s_alpha[row0 + 8];
#pragma unroll
                for (int nt = 0; nt < 8; ++nt) {
                    int col = nbase + nt * 8 + tc;
                    float b0 = s_bias[col], b1 = s_bias[col + 1];
                    float* C = c[nt];
                    float v;
                    v = C[0] + b0; v = v >= 0.f ? v : 0.01f * v; stg[stg_idx(row0, col)]         = v * a0;
                    v = C[1] + b1; v = v >= 0.f ? v : 0.01f * v; stg[stg_idx(row0, col + 1)]     = v * a0;
                    v = C[2] + b0; v = v >= 0.f ? v : 0.01f * v; stg[stg_idx(row0 + 8, col)]     = v * a1;
                    v = C[3] + b1; v = v >= 0.f ? v : 0.01f * v; stg[stg_idx(row0 + 8, col + 1)] = v * a1;
                }
            }
            __syncthreads();
            // pool this 64-row half: 4 threads per column, 16 rows each
            {
                int col = tid & 127, q = (tid >> 7) & 3;
                int rb = ph * 64 + q * 16, re = rb + 16;
                float acc = stg[stg_idx(rb, col)];
                int cg = s_gid[rb];
                for (int r = rb + 1; r < re; ++r) {
                    int gr = s_gid[r];
                    if (gr != cg) {
                        atomicAdd(&d_pooled[((size_t)s * G + cg) * D + col], acc);
                        acc = 0.f; cg = gr;
                    }
                    acc += stg[stg_idx(r, col)];
                }
                atomicAdd(&d_pooled[((size_t)s * G + cg) * D + col], acc);
            }
            __syncthreads();
        }
    }
}

// ---------------- kernel E: xg update, 16 graphs per block ----------------
#define XG_B 16
__global__ void k_xg(const float* __restrict__ tr_w, const float* __restrict__ tr_b,
                     float* __restrict__ xg, int s) {
    __shared__ float cat[XG_B][2 * D];
    int t = threadIdx.x;
    int g0 = blockIdx.x * XG_B;
#pragma unroll
    for (int q = 0; q < XG_B; ++q) {
        cat[q][t]     = d_pooled[((size_t)s * G + g0 + q) * D + t];
        cat[q][D + t] = xg[(size_t)(g0 + q) * D + t];
    }
    __syncthreads();
    const float* W = tr_w + (size_t)s * 2 * D * D;
    float bias = tr_b[s * D + t];
    float acc[XG_B];
#pragma unroll
    for (int q = 0; q < XG_B; ++q) acc[q] = bias;
    for (int k = 0; k < 2 * D; ++k) {
        float w = W[(size_t)k * D + t];
#pragma unroll
        for (int q = 0; q < XG_B; ++q) acc[q] += cat[q][k] * w;
    }
#pragma unroll
    for (int q = 0; q < XG_B; ++q) {
        float v = acc[q] >= 0.f ? acc[q] : 0.01f * acc[q];
        xg[(size_t)(g0 + q) * D + t] = v + cat[q][D + t];
    }
}

// ---------------- host launcher ----------------
extern "C" void kernel_launch(void* const* d_in, const int* in_sizes, int n_in,
                              void* d_out, int out_size) {
    const float* x   = (const float*)d_in[0];
    const float* xg0 = (const float*)d_in[1];
    int N = in_sizes[0] / D;

    int bi = 4;
    for (int i = 1; i < n_in; ++i)
        if (in_sizes[i] == N) { bi = i; break; }
    const int* batch = (const int*)d_in[bi];

    int wi = -1;
    for (int i = 2; i + 5 < n_in; ++i)
        if (in_sizes[i] == S * D && in_sizes[i + 1] == S) { wi = i; break; }
    if (wi < 0) wi = (n_in >= 12) ? 6 : 5;
    const float* gate_w = (const float*)d_in[wi];
    const float* gate_b = (const float*)d_in[wi + 1];
    const float* feat_w = (const float*)d_in[wi + 2];
    const float* feat_b = (const float*)d_in[wi + 3];
    const float* tr_w   = (const float*)d_in[wi + 4];
    const float* tr_b   = (const float*)d_in[wi + 5];

    float* out_x  = (float*)d_out;
    float* out_xg = out_x + (size_t)N * D;

    cudaFuncSetAttribute(k_feat_pool, cudaFuncAttributeMaxDynamicSharedMemorySize, SMEM_TOTAL);

    k_gate_copy<<<(N + 7) / 8, 256>>>(x, gate_w, gate_b, out_x, N);
    k_misc<<<MISC_BLKS, 256>>>(xg0, out_xg, feat_w, batch, N);
    k_softmax<<<G, 128>>>(N);
    k_feat_pool<<<(N + 127) / 128, 512, SMEM_TOTAL>>>(x, feat_b, batch, N);
    for (int s = 0; s < S; ++s)
        k_xg<<<G / XG_B, 128>>>(tr_w, tr_b, out_xg, s);
}

// round 9
// speedup vs baseline: 2.8157x; 1.1046x over previous
#include <cuda_runtime.h>
#include <cuda_fp16.h>
#include <math.h>
#include <stdint.h>

#define D   128
#define G   4096
#define S   3
#define MAXN 1000000

// ---------------- device scratch ----------------
__device__ float d_gates[S * MAXN];
__device__ float d_alpha[S * MAXN];
__device__ int   d_segstart[G + 1];
__device__ float d_pooled[S * G * D];
__device__ __half d_wt_hi[S * D * D];   // W^T fp16  [s][n][k]

// ---------------- helpers ----------------
__device__ __forceinline__ uint32_t smem_u32(const void* p) {
    uint32_t a;
    asm("{ .reg .u64 t; cvta.to.shared.u64 t, %1; cvt.u32.u64 %0, t; }" : "=r"(a) : "l"(p));
    return a;
}

__device__ __forceinline__ void ldsm_x4(uint32_t* r, uint32_t addr) {
    asm volatile("ldmatrix.sync.aligned.m8n8.x4.shared.b16 {%0,%1,%2,%3}, [%4];"
                 : "=r"(r[0]), "=r"(r[1]), "=r"(r[2]), "=r"(r[3]) : "r"(addr));
}

__device__ __forceinline__ void mma16816(float* c, const uint32_t* a, uint32_t b0, uint32_t b1) {
    asm volatile(
        "mma.sync.aligned.m16n8k16.row.col.f32.f16.f16.f32 "
        "{%0,%1,%2,%3}, {%4,%5,%6,%7}, {%8,%9}, {%0,%1,%2,%3};"
        : "+f"(c[0]), "+f"(c[1]), "+f"(c[2]), "+f"(c[3])
        : "r"(a[0]), "r"(a[1]), "r"(a[2]), "r"(a[3]), "r"(b0), "r"(b1));
}

// swizzled byte offset within a [128 row][128 fp16] tile (row stride 256B)
__device__ __forceinline__ uint32_t swz(int row, int kbyte) {
    return ((uint32_t)row << 8) + ((uint32_t)kbyte ^ (((uint32_t)row & 7u) << 4));
}
// staging index (floats) in 64x128 fp32 buffer, conflict-free rows+cols
__device__ __forceinline__ uint32_t stg_idx(int row, int col) {
    return (((uint32_t)row & 63u) << 7) + ((uint32_t)col ^ ((uint32_t)row & 31u));
}

// ---------------- smem layout (bytes) ----------------
#define SM_A      0              // 32KB: x tile fp16
#define SM_B      32768          // 32KB: W^T fp16, aliased as staging after MMA
#define SM_ALPHA  65536
#define SM_BIAS   66048
#define SM_GID    66560
#define SMEM_TOTAL 67072

// ---------------- kernel A: gate dots + copy x -> out ----------------
__global__ void k_gate_copy(const float* __restrict__ x,
                            const float* __restrict__ gate_w,
                            const float* __restrict__ gate_b,
                            float* __restrict__ out_x, int N) {
    __shared__ float gw[S * D];
    int tid = threadIdx.x;
    for (int i = tid; i < S * D; i += blockDim.x) gw[i] = gate_w[i];
    __syncthreads();
    int lane = tid & 31;
    int node = blockIdx.x * (blockDim.x >> 5) + (tid >> 5);
    if (node >= N) return;
    const float4 v = ((const float4*)(x + (size_t)node * D))[lane];
    ((float4*)(out_x + (size_t)node * D))[lane] = v;
#pragma unroll
    for (int s = 0; s < S; ++s) {
        const float* g = gw + s * D + lane * 4;
        float d = v.x * g[0] + v.y * g[1] + v.z * g[2] + v.w * g[3];
#pragma unroll
        for (int o = 16; o > 0; o >>= 1) d += __shfl_xor_sync(0xffffffffu, d, o);
        if (lane == 0) d_gates[s * N + node] = d + gate_b[s];
    }
}

// ---------------- merged small kernel: copy_xg + prep_w + segstart ----------------
#define MISC_COPY_BLKS  (G * D / 256)             // 2048
#define MISC_PREP_BLKS  ((S * D * D + 255) / 256) // 192
#define MISC_SEG_BLKS   ((G + 256) / 256)         // 17
#define MISC_BLKS (MISC_COPY_BLKS + MISC_PREP_BLKS + MISC_SEG_BLKS)
__global__ void k_misc(const float* __restrict__ xg, float* __restrict__ out_xg,
                       const float* __restrict__ feat_w,
                       const int* __restrict__ batch, int N) {
    int b = blockIdx.x, t = threadIdx.x;
    if (b < MISC_COPY_BLKS) {
        out_xg[b * 256 + t] = xg[b * 256 + t];
    } else if (b < MISC_COPY_BLKS + MISC_PREP_BLKS) {
        int i = (b - MISC_COPY_BLKS) * 256 + t;
        if (i < S * D * D) {
            int s = i / (D * D), r = i % (D * D);
            int n = r / D, k = r % D;
            d_wt_hi[i] = __float2half_rn(feat_w[s * D * D + k * D + n]);
        }
    } else {
        int g = (b - MISC_COPY_BLKS - MISC_PREP_BLKS) * 256 + t;
        if (g > G) return;
        if (g == G) { d_segstart[G] = N; return; }
        int lo = 0, hi = N;
        while (lo < hi) {
            int mid = (lo + hi) >> 1;
            if (batch[mid] < g) lo = mid + 1; else hi = mid;
        }
        d_segstart[g] = lo;
    }
}

// ---------------- kernel C: per-graph softmax -> alpha; zero pooled ----------------
__global__ void k_softmax(int N) {
    int g = blockIdx.x, t = threadIdx.x;
#pragma unroll
    for (int s = 0; s < S; ++s) d_pooled[(s * G + g) * D + t] = 0.f;
    int a = d_segstart[g], b = d_segstart[g + 1];
    if (a >= b) return;
    __shared__ float red[S][4];
    int wid = t >> 5, lane = t & 31;
    float mx[S];
#pragma unroll
    for (int s = 0; s < S; ++s) mx[s] = -INFINITY;
    for (int i = a + t; i < b; i += 128)
#pragma unroll
        for (int s = 0; s < S; ++s) mx[s] = fmaxf(mx[s], d_gates[s * N + i]);
#pragma unroll
    for (int s = 0; s < S; ++s) {
#pragma unroll
        for (int o = 16; o > 0; o >>= 1) mx[s] = fmaxf(mx[s], __shfl_xor_sync(~0u, mx[s], o));
        if (lane == 0) red[s][wid] = mx[s];
    }
    __syncthreads();
#pragma unroll
    for (int s = 0; s < S; ++s)
        mx[s] = fmaxf(fmaxf(red[s][0], red[s][1]), fmaxf(red[s][2], red[s][3]));
    __syncthreads();
    float sm[S] = {0.f, 0.f, 0.f};
    for (int i = a + t; i < b; i += 128)
#pragma unroll
        for (int s = 0; s < S; ++s) sm[s] += expf(d_gates[s * N + i] - mx[s]);
#pragma unroll
    for (int s = 0; s < S; ++s) {
#pragma unroll
        for (int o = 16; o > 0; o >>= 1) sm[s] += __shfl_xor_sync(~0u, sm[s], o);
        if (lane == 0) red[s][wid] = sm[s];
    }
    __syncthreads();
    float inv[S];
#pragma unroll
    for (int s = 0; s < S; ++s)
        inv[s] = 1.f / (red[s][0] + red[s][1] + red[s][2] + red[s][3]);
    for (int i = a + t; i < b; i += 128)
#pragma unroll
        for (int s = 0; s < S; ++s)
            d_alpha[s * N + i] = expf(d_gates[s * N + i] - mx[s]) * inv[s];
}

// ---------------- kernel D: single-pass fp16 HMMA, 512 threads, 2 CTAs/SM ----------------
__global__ void __launch_bounds__(512, 2)
k_feat_pool(const float* __restrict__ x,
            const float* __restrict__ feat_b,
            const int* __restrict__ batch, int N) {
    extern __shared__ char smem[];
    uint32_t sm = smem_u32(smem);
    float* stg     = (float*)(smem + SM_B);
    float* s_alpha = (float*)(smem + SM_ALPHA);
    float* s_bias  = (float*)(smem + SM_BIAS);
    int*   s_gid   = (int*)(smem + SM_GID);

    int tid = threadIdx.x;
    int wid = tid >> 5, lane = tid & 31;
    int r0 = blockIdx.x * 128;
    int rows = min(128, N - r0);

    // load x tile, fp32 -> fp16 into swizzled smem (zero-padded)
#pragma unroll
    for (int i = 0; i < 8; ++i) {
        int idx = i * 512 + tid;           // 4096 float4
        int row = idx >> 5, j = idx & 31;
        float4 v = make_float4(0.f, 0.f, 0.f, 0.f);
        if (row < rows) v = ((const float4*)(x + (size_t)(r0 + row) * D))[j];
        __half h0 = __float2half_rn(v.x), h1 = __float2half_rn(v.y);
        __half h2 = __float2half_rn(v.z), h3 = __float2half_rn(v.w);
        uint2 hp;
        hp.x = (uint32_t)__half_as_ushort(h0) | ((uint32_t)__half_as_ushort(h1) << 16);
        hp.y = (uint32_t)__half_as_ushort(h2) | ((uint32_t)__half_as_ushort(h3) << 16);
        *(uint2*)(smem + SM_A + swz(row, j * 8)) = hp;
    }
    if (tid < 128) {
        int rr = min(tid, rows - 1);
        s_gid[tid] = batch[r0 + rr];
    }

    // warp tiling: 4 m-blocks (32 rows) x 4 n-blocks (32 cols), 16 warps
    int mbase = (wid & 3) * 32;
    int nbase = (wid >> 2) * 32;
    int r15 = lane & 15;
    uint32_t swx = ((uint32_t)lane & 7u) << 4;
    int khalf = (lane >> 4) << 4;
    int grp   = lane >> 2, tc = (lane & 3) * 2;
    bool halfA = (wid & 3) < 2;     // warp owns rows 0..63

#pragma unroll 1
    for (int s = 0; s < S; ++s) {
        __syncthreads();   // prev pooling / x-store visible; B region free
        // ---- load B (W^T fp16), once per step ----
        {
            const uint4* wh = (const uint4*)(d_wt_hi + s * D * D);
#pragma unroll
            for (int i = 0; i < 4; ++i) {
                int idx = i * 512 + tid;
                int row = idx >> 4, kb = (idx & 15) * 16;
                *(uint4*)(smem + SM_B + swz(row, kb)) = wh[idx];
            }
        }
        if (tid < 128) {
            s_bias[tid]  = feat_b[s * D + tid];
            s_alpha[tid] = (tid < rows) ? d_alpha[s * N + r0 + tid] : 0.f;
        }
        __syncthreads();

        float c[8][4];   // [mi*4 + nq*2 + j][4]
#pragma unroll
        for (int i = 0; i < 8; ++i)
#pragma unroll
            for (int j = 0; j < 4; ++j) c[i][j] = 0.f;

        // ---- single pass: c = x_hi * W_hi ----
#pragma unroll
        for (int ks = 0; ks < 8; ++ks) {
            int kb = ks * 32 + khalf;
            uint32_t ah[2][4];
#pragma unroll
            for (int mi = 0; mi < 2; ++mi) {
                uint32_t aoff = ((uint32_t)(mbase + mi * 16 + r15) << 8) + ((uint32_t)kb ^ swx);
                ldsm_x4(ah[mi], sm + SM_A + aoff);
            }
#pragma unroll
            for (int nq = 0; nq < 2; ++nq) {
                uint32_t bh[4];
                uint32_t boff = ((uint32_t)(nbase + nq * 16 + r15) << 8) + ((uint32_t)kb ^ swx);
                ldsm_x4(bh, sm + SM_B + boff);
#pragma unroll
                for (int mi = 0; mi < 2; ++mi) {
                    mma16816(c[mi * 4 + nq * 2],     ah[mi], bh[0], bh[2]);
                    mma16816(c[mi * 4 + nq * 2 + 1], ah[mi], bh[1], bh[3]);
                }
            }
        }
        __syncthreads();   // B reads done; B region becomes staging

        // ---- two-phase epilogue + pooling over 64-row halves ----
#pragma unroll
        for (int ph = 0; ph < 2; ++ph) {
            if ((ph == 0) == halfA) {   // phase 0: rows 0-63, phase 1: rows 64-127
#pragma unroll
                for (int mi = 0; mi < 2; ++mi) {
                    int row0 = mbase + mi * 16 + grp;   // GLOBAL row (0..127)
                    float a0 = s_alpha[row0], a1 = s_alpha[row0 + 8];
#pragma unroll
                    for (int nq = 0; nq < 2; ++nq) {
#pragma unroll
                        for (int j = 0; j < 2; ++j) {
                            int col = nbase + nq * 16 + j * 8 + tc;
                            float b0 = s_bias[col], b1 = s_bias[col + 1];
                            float* C = c[mi * 4 + nq * 2 + j];
                            float v;
                            v = C[0] + b0; v = v >= 0.f ? v : 0.01f * v; stg[stg_idx(row0, col)]         = v * a0;
                            v = C[1] + b1; v = v >= 0.f ? v : 0.01f * v; stg[stg_idx(row0, col + 1)]     = v * a0;
                            v = C[2] + b0; v = v >= 0.f ? v : 0.01f * v; stg[stg_idx(row0 + 8, col)]     = v * a1;
                            v = C[3] + b1; v = v >= 0.f ? v : 0.01f * v; stg[stg_idx(row0 + 8, col + 1)] = v * a1;
                        }
                    }
                }
            }
            __syncthreads();
            // pool this 64-row half: 4 threads per column, 16 rows each
            {
                int col = tid & 127, q = (tid >> 7) & 3;
                int rb = ph * 64 + q * 16, re = rb + 16;
                float acc = stg[stg_idx(rb, col)];
                int cg = s_gid[rb];
                for (int r = rb + 1; r < re; ++r) {
                    int gr = s_gid[r];
                    if (gr != cg) {
                        atomicAdd(&d_pooled[((size_t)s * G + cg) * D + col], acc);
                        acc = 0.f; cg = gr;
                    }
                    acc += stg[stg_idx(r, col)];
                }
                atomicAdd(&d_pooled[((size_t)s * G + cg) * D + col], acc);
            }
            __syncthreads();
        }
    }
}

// ---------------- kernel E: xg update, 16 graphs per block ----------------
#define XG_B 16
__global__ void k_xg(const float* __restrict__ tr_w, const float* __restrict__ tr_b,
                     float* __restrict__ xg, int s) {
    __shared__ float cat[XG_B][2 * D];
    int t = threadIdx.x;
    int g0 = blockIdx.x * XG_B;
#pragma unroll
    for (int q = 0; q < XG_B; ++q) {
        cat[q][t]     = d_pooled[((size_t)s * G + g0 + q) * D + t];
        cat[q][D + t] = xg[(size_t)(g0 + q) * D + t];
    }
    __syncthreads();
    const float* W = tr_w + (size_t)s * 2 * D * D;
    float bias = tr_b[s * D + t];
    float acc[XG_B];
#pragma unroll
    for (int q = 0; q < XG_B; ++q) acc[q] = bias;
    for (int k = 0; k < 2 * D; ++k) {
        float w = W[(size_t)k * D + t];
#pragma unroll
        for (int q = 0; q < XG_B; ++q) acc[q] += cat[q][k] * w;
    }
#pragma unroll
    for (int q = 0; q < XG_B; ++q) {
        float v = acc[q] >= 0.f ? acc[q] : 0.01f * acc[q];
        xg[(size_t)(g0 + q) * D + t] = v + cat[q][D + t];
    }
}

// ---------------- host launcher ----------------
extern "C" void kernel_launch(void* const* d_in, const int* in_sizes, int n_in,
                              void* d_out, int out_size) {
    const float* x   = (const float*)d_in[0];
    const float* xg0 = (const float*)d_in[1];
    int N = in_sizes[0] / D;

    int bi = 4;
    for (int i = 1; i < n_in; ++i)
        if (in_sizes[i] == N) { bi = i; break; }
    const int* batch = (const int*)d_in[bi];

    int wi = -1;
    for (int i = 2; i + 5 < n_in; ++i)
        if (in_sizes[i] == S * D && in_sizes[i + 1] == S) { wi = i; break; }
    if (wi < 0) wi = (n_in >= 12) ? 6 : 5;
    const float* gate_w = (const float*)d_in[wi];
    const float* gate_b = (const float*)d_in[wi + 1];
    const float* feat_w = (const float*)d_in[wi + 2];
    const float* feat_b = (const float*)d_in[wi + 3];
    const float* tr_w   = (const float*)d_in[wi + 4];
    const float* tr_b   = (const float*)d_in[wi + 5];

    float* out_x  = (float*)d_out;
    float* out_xg = out_x + (size_t)N * D;

    cudaFuncSetAttribute(k_feat_pool, cudaFuncAttributeMaxDynamicSharedMemorySize, SMEM_TOTAL);

    k_gate_copy<<<(N + 7) / 8, 256>>>(x, gate_w, gate_b, out_x, N);
    k_misc<<<MISC_BLKS, 256>>>(xg0, out_xg, feat_w, batch, N);
    k_softmax<<<G, 128>>>(N);
    k_feat_pool<<<(N + 127) / 128, 512, SMEM_TOTAL>>>(x, feat_b, batch, N);
    for (int s = 0; s < S; ++s)
        k_xg<<<G / XG_B, 128>>>(tr_w, tr_b, out_xg, s);
}

// round 10
// speedup vs baseline: 3.8958x; 1.3836x over previous
#include <cuda_runtime.h>
#include <cuda_fp16.h>
#include <math.h>
#include <stdint.h>

#define D   128
#define G   4096
#define S   3
#define MAXN 1000000

// ---------------- device scratch ----------------
__device__ float d_gates[S * MAXN];
__device__ float d_alpha[S * MAXN];
__device__ int   d_segstart[G + 1];
__device__ float d_pooled[S * G * D];
__device__ __half d_wt_hi[S * D * D];   // W^T fp16  [s][n][k]
__device__ __half d_x16[(size_t)MAXN * D];  // x pre-converted to fp16

// ---------------- helpers ----------------
__device__ __forceinline__ uint32_t smem_u32(const void* p) {
    uint32_t a;
    asm("{ .reg .u64 t; cvta.to.shared.u64 t, %1; cvt.u32.u64 %0, t; }" : "=r"(a) : "l"(p));
    return a;
}

__device__ __forceinline__ void ldsm_x4(uint32_t* r, uint32_t addr) {
    asm volatile("ldmatrix.sync.aligned.m8n8.x4.shared.b16 {%0,%1,%2,%3}, [%4];"
                 : "=r"(r[0]), "=r"(r[1]), "=r"(r[2]), "=r"(r[3]) : "r"(addr));
}

__device__ __forceinline__ void mma16816(float* c, const uint32_t* a, uint32_t b0, uint32_t b1) {
    asm volatile(
        "mma.sync.aligned.m16n8k16.row.col.f32.f16.f16.f32 "
        "{%0,%1,%2,%3}, {%4,%5,%6,%7}, {%8,%9}, {%0,%1,%2,%3};"
        : "+f"(c[0]), "+f"(c[1]), "+f"(c[2]), "+f"(c[3])
        : "r"(a[0]), "r"(a[1]), "r"(a[2]), "r"(a[3]), "r"(b0), "r"(b1));
}

__device__ __forceinline__ void cp_async16(uint32_t dst, const void* src, int src_bytes) {
    asm volatile("cp.async.cg.shared.global [%0], [%1], 16, %2;"
                 :: "r"(dst), "l"(src), "r"(src_bytes) : "memory");
}
#define CP_COMMIT() asm volatile("cp.async.commit_group;" ::: "memory")
#define CP_WAIT0()  asm volatile("cp.async.wait_group 0;" ::: "memory")

// swizzled byte offset within a [128 row][128 fp16] tile (row stride 256B)
__device__ __forceinline__ uint32_t swz(int row, int kbyte) {
    return ((uint32_t)row << 8) + ((uint32_t)kbyte ^ (((uint32_t)row & 7u) << 4));
}

// ---------------- smem layout (bytes) ----------------
#define SM_A      0              // 32KB: x tile fp16 (persistent across steps)
#define SM_B      32768          // 32KB: W^T fp16 (double-use via cp.async pipeline)
#define SM_STG    65536          // 34KB: fp16 staging, 128 rows x 136-half stride
#define SM_ALPHA  100352         // 3*128 fp32
#define SM_BIAS   101888         // 3*128 fp32
#define SM_GID    103424         // 128 int
#define SMEM_TOTAL 103936
#define STG_LDH   136            // halves per staging row

// ---------------- kernel A: gate dots + copy x -> out + x fp16 ----------------
__global__ void k_gate_copy(const float* __restrict__ x,
                            const float* __restrict__ gate_w,
                            const float* __restrict__ gate_b,
                            float* __restrict__ out_x, int N) {
    __shared__ float gw[S * D];
    int tid = threadIdx.x;
    for (int i = tid; i < S * D; i += blockDim.x) gw[i] = gate_w[i];
    __syncthreads();
    int lane = tid & 31;
    int node = blockIdx.x * (blockDim.x >> 5) + (tid >> 5);
    if (node >= N) return;
    const float4 v = ((const float4*)(x + (size_t)node * D))[lane];
    ((float4*)(out_x + (size_t)node * D))[lane] = v;
    uint2 hp;
    hp.x = (uint32_t)__half_as_ushort(__float2half_rn(v.x)) |
           ((uint32_t)__half_as_ushort(__float2half_rn(v.y)) << 16);
    hp.y = (uint32_t)__half_as_ushort(__float2half_rn(v.z)) |
           ((uint32_t)__half_as_ushort(__float2half_rn(v.w)) << 16);
    ((uint2*)(d_x16 + (size_t)node * D))[lane] = hp;
#pragma unroll
    for (int s = 0; s < S; ++s) {
        const float* g = gw + s * D + lane * 4;
        float d = v.x * g[0] + v.y * g[1] + v.z * g[2] + v.w * g[3];
#pragma unroll
        for (int o = 16; o > 0; o >>= 1) d += __shfl_xor_sync(0xffffffffu, d, o);
        if (lane == 0) d_gates[s * N + node] = d + gate_b[s];
    }
}

// ---------------- merged small kernel: copy_xg + prep_w + segstart ----------------
#define MISC_COPY_BLKS  (G * D / 256)             // 2048
#define MISC_PREP_BLKS  ((S * D * D + 255) / 256) // 192
#define MISC_SEG_BLKS   ((G + 256) / 256)         // 17
#define MISC_BLKS (MISC_COPY_BLKS + MISC_PREP_BLKS + MISC_SEG_BLKS)
__global__ void k_misc(const float* __restrict__ xg, float* __restrict__ out_xg,
                       const float* __restrict__ feat_w,
                       const int* __restrict__ batch, int N) {
    int b = blockIdx.x, t = threadIdx.x;
    if (b < MISC_COPY_BLKS) {
        out_xg[b * 256 + t] = xg[b * 256 + t];
    } else if (b < MISC_COPY_BLKS + MISC_PREP_BLKS) {
        int i = (b - MISC_COPY_BLKS) * 256 + t;
        if (i < S * D * D) {
            int s = i / (D * D), r = i % (D * D);
            int n = r / D, k = r % D;
            d_wt_hi[i] = __float2half_rn(feat_w[s * D * D + k * D + n]);
        }
    } else {
        int g = (b - MISC_COPY_BLKS - MISC_PREP_BLKS) * 256 + t;
        if (g > G) return;
        if (g == G) { d_segstart[G] = N; return; }
        int lo = 0, hi = N;
        while (lo < hi) {
            int mid = (lo + hi) >> 1;
            if (batch[mid] < g) lo = mid + 1; else hi = mid;
        }
        d_segstart[g] = lo;
    }
}

// ---------------- kernel C: per-graph softmax -> alpha; zero pooled ----------------
__global__ void k_softmax(int N) {
    int g = blockIdx.x, t = threadIdx.x;
#pragma unroll
    for (int s = 0; s < S; ++s) d_pooled[(s * G + g) * D + t] = 0.f;
    int a = d_segstart[g], b = d_segstart[g + 1];
    if (a >= b) return;
    __shared__ float red[S][4];
    int wid = t >> 5, lane = t & 31;
    float mx[S];
#pragma unroll
    for (int s = 0; s < S; ++s) mx[s] = -INFINITY;
    for (int i = a + t; i < b; i += 128)
#pragma unroll
        for (int s = 0; s < S; ++s) mx[s] = fmaxf(mx[s], d_gates[s * N + i]);
#pragma unroll
    for (int s = 0; s < S; ++s) {
#pragma unroll
        for (int o = 16; o > 0; o >>= 1) mx[s] = fmaxf(mx[s], __shfl_xor_sync(~0u, mx[s], o));
        if (lane == 0) red[s][wid] = mx[s];
    }
    __syncthreads();
#pragma unroll
    for (int s = 0; s < S; ++s)
        mx[s] = fmaxf(fmaxf(red[s][0], red[s][1]), fmaxf(red[s][2], red[s][3]));
    __syncthreads();
    float sm[S] = {0.f, 0.f, 0.f};
    for (int i = a + t; i < b; i += 128)
#pragma unroll
        for (int s = 0; s < S; ++s) sm[s] += expf(d_gates[s * N + i] - mx[s]);
#pragma unroll
    for (int s = 0; s < S; ++s) {
#pragma unroll
        for (int o = 16; o > 0; o >>= 1) sm[s] += __shfl_xor_sync(~0u, sm[s], o);
        if (lane == 0) red[s][wid] = sm[s];
    }
    __syncthreads();
    float inv[S];
#pragma unroll
    for (int s = 0; s < S; ++s)
        inv[s] = 1.f / (red[s][0] + red[s][1] + red[s][2] + red[s][3]);
    for (int i = a + t; i < b; i += 128)
#pragma unroll
        for (int s = 0; s < S; ++s)
            d_alpha[s * N + i] = expf(d_gates[s * N + i] - mx[s]) * inv[s];
}

// ---------------- kernel D: pipelined fp16 HMMA, fp16 staging, 2 CTAs/SM ----------------
__global__ void __launch_bounds__(512, 2)
k_feat_pool(const float* __restrict__ feat_b,
            const int* __restrict__ batch, int N) {
    extern __shared__ char smem[];
    uint32_t sm = smem_u32(smem);
    __half* stg    = (__half*)(smem + SM_STG);
    float* s_alpha = (float*)(smem + SM_ALPHA);
    float* s_bias  = (float*)(smem + SM_BIAS);
    int*   s_gid   = (int*)(smem + SM_GID);

    int tid = threadIdx.x;
    int wid = tid >> 5, lane = tid & 31;
    int r0 = blockIdx.x * 128;
    int rows = min(128, N - r0);

    // ---- prologue: cp.async A tile (fp16, pre-split) + B(0) ----
#pragma unroll
    for (int i = 0; i < 4; ++i) {
        int idx = i * 512 + tid;           // 2048 x 16B
        int row = idx >> 4, kpart = idx & 15;
        cp_async16(sm + SM_A + swz(row, kpart * 16),
                   d_x16 + (size_t)(r0 + row) * D + kpart * 8,
                   (row < rows) ? 16 : 0);
    }
    {
        const __half* wh = d_wt_hi;        // step 0
#pragma unroll
        for (int i = 0; i < 4; ++i) {
            int idx = i * 512 + tid;
            int row = idx >> 4, kpart = idx & 15;
            cp_async16(sm + SM_B + swz(row, kpart * 16), wh + row * D + kpart * 8, 16);
        }
    }
    CP_COMMIT();

    // prefetch alpha/bias for all 3 steps + gid
    if (tid < 384) {
        int s = tid >> 7, t = tid & 127;
        s_bias[tid]  = feat_b[s * D + t];
        s_alpha[tid] = (t < rows) ? d_alpha[s * N + r0 + t] : 0.f;
    }
    if (tid < 128) {
        int rr = min(tid, rows - 1);
        s_gid[tid] = batch[r0 + rr];
    }

    // warp tiling: 4 m-blocks (32 rows) x 4 n-blocks (32 cols), 16 warps
    int mbase = (wid & 3) * 32;
    int nbase = (wid >> 2) * 32;
    int r15 = lane & 15;
    uint32_t swx = ((uint32_t)lane & 7u) << 4;
    int khalf = (lane >> 4) << 4;
    int grp   = lane >> 2, tc = (lane & 3) * 2;

#pragma unroll 1
    for (int s = 0; s < S; ++s) {
        CP_WAIT0();
        __syncthreads();   // B(s) + (s==0: A, alpha, bias, gid) ready; stg free

        float c[8][4];   // [mi*4 + nq*2 + j][4]
#pragma unroll
        for (int i = 0; i < 8; ++i)
#pragma unroll
            for (int j = 0; j < 4; ++j) c[i][j] = 0.f;

        // ---- MMA: c = x_hi * W_hi ----
#pragma unroll
        for (int ks = 0; ks < 8; ++ks) {
            int kb = ks * 32 + khalf;
            uint32_t ah[2][4];
#pragma unroll
            for (int mi = 0; mi < 2; ++mi) {
                uint32_t aoff = ((uint32_t)(mbase + mi * 16 + r15) << 8) + ((uint32_t)kb ^ swx);
                ldsm_x4(ah[mi], sm + SM_A + aoff);
            }
#pragma unroll
            for (int nq = 0; nq < 2; ++nq) {
                uint32_t bh[4];
                uint32_t boff = ((uint32_t)(nbase + nq * 16 + r15) << 8) + ((uint32_t)kb ^ swx);
                ldsm_x4(bh, sm + SM_B + boff);
#pragma unroll
                for (int mi = 0; mi < 2; ++mi) {
                    mma16816(c[mi * 4 + nq * 2],     ah[mi], bh[0], bh[2]);
                    mma16816(c[mi * 4 + nq * 2 + 1], ah[mi], bh[1], bh[3]);
                }
            }
        }
        __syncthreads();   // all warps done reading B(s)

        // ---- prefetch B(s+1), overlapped with epilogue + pooling ----
        if (s + 1 < S) {
            const __half* wh = d_wt_hi + (s + 1) * D * D;
#pragma unroll
            for (int i = 0; i < 4; ++i) {
                int idx = i * 512 + tid;
                int row = idx >> 4, kpart = idx & 15;
                cp_async16(sm + SM_B + swz(row, kpart * 16), wh + row * D + kpart * 8, 16);
            }
            CP_COMMIT();
        }

        // ---- single-phase epilogue: bias + leaky + alpha -> fp16 staging ----
#pragma unroll
        for (int mi = 0; mi < 2; ++mi) {
            int row0 = mbase + mi * 16 + grp;
            float a0 = s_alpha[s * 128 + row0], a1 = s_alpha[s * 128 + row0 + 8];
#pragma unroll
            for (int nq = 0; nq < 2; ++nq) {
#pragma unroll
                for (int j = 0; j < 2; ++j) {
                    int col = nbase + nq * 16 + j * 8 + tc;
                    float b0 = s_bias[s * 128 + col], b1 = s_bias[s * 128 + col + 1];
                    float* C = c[mi * 4 + nq * 2 + j];
                    float v0 = C[0] + b0; v0 = v0 >= 0.f ? v0 : 0.01f * v0;
                    float v1 = C[1] + b1; v1 = v1 >= 0.f ? v1 : 0.01f * v1;
                    float v2 = C[2] + b0; v2 = v2 >= 0.f ? v2 : 0.01f * v2;
                    float v3 = C[3] + b1; v3 = v3 >= 0.f ? v3 : 0.01f * v3;
                    *(__half2*)(stg + row0 * STG_LDH + col) =
                        __floats2half2_rn(v0 * a0, v1 * a0);
                    *(__half2*)(stg + (row0 + 8) * STG_LDH + col) =
                        __floats2half2_rn(v2 * a1, v3 * a1);
                }
            }
        }
        __syncthreads();   // staging complete

        // ---- pooling: 512 threads, 2 cols each (half2), 16-row chunks ----
        {
            int c0 = (tid & 63) * 2;
            int rb = (tid >> 6) * 16, re = rb + 16;
            float2 f = __half22float2(*(__half2*)(stg + rb * STG_LDH + c0));
            float acc0 = f.x, acc1 = f.y;
            int cg = s_gid[rb];
            for (int r = rb + 1; r < re; ++r) {
                int gr = s_gid[r];
                if (gr != cg) {
                    size_t base = ((size_t)s * G + cg) * D;
                    atomicAdd(&d_pooled[base + c0], acc0);
                    atomicAdd(&d_pooled[base + c0 + 1], acc1);
                    acc0 = 0.f; acc1 = 0.f; cg = gr;
                }
                float2 g2 = __half22float2(*(__half2*)(stg + r * STG_LDH + c0));
                acc0 += g2.x; acc1 += g2.y;
            }
            size_t base = ((size_t)s * G + cg) * D;
            atomicAdd(&d_pooled[base + c0], acc0);
            atomicAdd(&d_pooled[base + c0 + 1], acc1);
        }
        // next-iteration top sync protects stg + B reuse
    }
}

// ---------------- kernel E: xg update, 16 graphs per block ----------------
#define XG_B 16
__global__ void k_xg(const float* __restrict__ tr_w, const float* __restrict__ tr_b,
                     float* __restrict__ xg, int s) {
    __shared__ float cat[XG_B][2 * D];
    int t = threadIdx.x;
    int g0 = blockIdx.x * XG_B;
#pragma unroll
    for (int q = 0; q < XG_B; ++q) {
        cat[q][t]     = d_pooled[((size_t)s * G + g0 + q) * D + t];
        cat[q][D + t] = xg[(size_t)(g0 + q) * D + t];
    }
    __syncthreads();
    const float* W = tr_w + (size_t)s * 2 * D * D;
    float bias = tr_b[s * D + t];
    float acc[XG_B];
#pragma unroll
    for (int q = 0; q < XG_B; ++q) acc[q] = bias;
    for (int k = 0; k < 2 * D; ++k) {
        float w = W[(size_t)k * D + t];
#pragma unroll
        for (int q = 0; q < XG_B; ++q) acc[q] += cat[q][k] * w;
    }
#pragma unroll
    for (int q = 0; q < XG_B; ++q) {
        float v = acc[q] >= 0.f ? acc[q] : 0.01f * acc[q];
        xg[(size_t)(g0 + q) * D + t] = v + cat[q][D + t];
    }
}

// ---------------- host launcher ----------------
extern "C" void kernel_launch(void* const* d_in, const int* in_sizes, int n_in,
                              void* d_out, int out_size) {
    const float* x   = (const float*)d_in[0];
    const float* xg0 = (const float*)d_in[1];
    int N = in_sizes[0] / D;

    int bi = 4;
    for (int i = 1; i < n_in; ++i)
        if (in_sizes[i] == N) { bi = i; break; }
    const int* batch = (const int*)d_in[bi];

    int wi = -1;
    for (int i = 2; i + 5 < n_in; ++i)
        if (in_sizes[i] == S * D && in_sizes[i + 1] == S) { wi = i; break; }
    if (wi < 0) wi = (n_in >= 12) ? 6 : 5;
    const float* gate_w = (const float*)d_in[wi];
    const float* gate_b = (const float*)d_in[wi + 1];
    const float* feat_w = (const float*)d_in[wi + 2];
    const float* feat_b = (const float*)d_in[wi + 3];
    const float* tr_w   = (const float*)d_in[wi + 4];
    const float* tr_b   = (const float*)d_in[wi + 5];

    float* out_x  = (float*)d_out;
    float* out_xg = out_x + (size_t)N * D;

    cudaFuncSetAttribute(k_feat_pool, cudaFuncAttributeMaxDynamicSharedMemorySize, SMEM_TOTAL);

    k_gate_copy<<<(N + 7) / 8, 256>>>(x, gate_w, gate_b, out_x, N);
    k_misc<<<MISC_BLKS, 256>>>(xg0, out_xg, feat_w, batch, N);
    k_softmax<<<G, 128>>>(N);
    k_feat_pool<<<(N + 127) / 128, 512, SMEM_TOTAL>>>(feat_b, batch, N);
    for (int s = 0; s < S; ++s)
        k_xg<<<G / XG_B, 128>>>(tr_w, tr_b, out_xg, s);
}